// round 3
// baseline (speedup 1.0000x reference)
#include <cuda_runtime.h>
#include <cstddef>

// Problem constants
#define BB 512
#define TT 256
#define DD 128
#define HH 128
#define SS 32
#define BT (BB*TT)   // 131072

// ---------------------------------------------------------------------------
// Device-global scratch (no cudaMalloc allowed)
// ---------------------------------------------------------------------------
__device__ float g_Xz[(size_t)BT * HH];   // 64 MiB
__device__ float g_Xr[(size_t)BT * HH];
__device__ float g_Xh[(size_t)BT * HH];
__device__ float g_gh[(size_t)BT * HH];
__device__ float g_WT[7 * DD * HH];       // transposed weights: [k][j] layout
// order: 0=WzT 1=VzT 2=WrT 3=VrT 4=WhT 5=VhT 6=WdghT

// ---------------------------------------------------------------------------
// Kernel 0: transpose the 7 input-projection weight matrices [j][k] -> [k][j]
// ---------------------------------------------------------------------------
__global__ void transpose_weights(const float* __restrict__ Wz, const float* __restrict__ Vz,
                                  const float* __restrict__ Wr, const float* __restrict__ Vr,
                                  const float* __restrict__ Wh, const float* __restrict__ Vh,
                                  const float* __restrict__ Wdgh)
{
    const float* srcs[7] = {Wz, Vz, Wr, Vr, Wh, Vh, Wdgh};
    const float* src = srcs[blockIdx.x];
    float* dst = g_WT + blockIdx.x * (DD * HH);
    for (int idx = threadIdx.x; idx < DD * HH; idx += blockDim.x) {
        int d = idx >> 7;
        int j = idx & 127;
        dst[idx] = src[j * DD + d];
    }
}

// ---------------------------------------------------------------------------
// Kernel 1: precompute (parallel over all (b,t))
//   x_hat, then Xg = x_hat@Wg.T + m@Vg.T + bg for g in {z,r,h}
//   gamma_h = exp(-relu(delta@Wdgh.T + b_dgh))
// Block = 128 rows of (b,t); 256 threads; 8x8 register micro-tiles.
// ---------------------------------------------------------------------------
#define APAD 129
#define SMEM_A_SZ (128 * APAD)          // one A panel (transposed, padded)

__device__ __forceinline__ void gemm_accum(const float* __restrict__ As,
                                           const float* __restrict__ WT,
                                           float* __restrict__ Bs,
                                           float acc[8][8],
                                           int tid, int r0, int j0)
{
    #pragma unroll 1
    for (int kt = 0; kt < 4; kt++) {
        // stage 32x128 weight tile (contiguous copy; WT already [k][j])
        for (int idx = tid; idx < 32 * 128; idx += 256)
            Bs[idx] = WT[kt * 32 * 128 + idx];
        __syncthreads();
        #pragma unroll
        for (int d = 0; d < 32; d++) {
            float a[8], bv[8];
            // A fragment: scalar LDS (16 lanes/ty broadcast, conflict-free).
            // MUST be scalar: base index (kt*32+d)*129 + r0 is not 16B aligned.
            const float* arow = &As[(kt * 32 + d) * APAD + r0];
            #pragma unroll
            for (int i = 0; i < 8; i++) a[i] = arow[i];
            // B fragment: aligned float4 (d*128 + j0, j0 = tx*8)
            *(float4*)&bv[0] = *(const float4*)&Bs[d * 128 + j0];
            *(float4*)&bv[4] = *(const float4*)&Bs[d * 128 + j0 + 4];
            #pragma unroll
            for (int i = 0; i < 8; i++)
                #pragma unroll
                for (int jj = 0; jj < 8; jj++)
                    acc[i][jj] = fmaf(a[i], bv[jj], acc[i][jj]);
        }
        __syncthreads();
    }
}

__global__ __launch_bounds__(256, 1)
void precompute_kernel(const float* __restrict__ x,     const float* __restrict__ mask,
                       const float* __restrict__ delta, const float* __restrict__ xlast,
                       const float* __restrict__ x_mean,
                       const float* __restrict__ w_dg_x, const float* __restrict__ b_dg_x,
                       const float* __restrict__ b_dg_h,
                       const float* __restrict__ b_z, const float* __restrict__ b_r,
                       const float* __restrict__ b_h)
{
    extern __shared__ float sm[];
    float* As_x = sm;
    float* As_m = sm + SMEM_A_SZ;
    float* As_d = sm + 2 * SMEM_A_SZ;
    float* Bs   = sm + 3 * SMEM_A_SZ;    // 32*128 floats

    const int tid  = threadIdx.x;
    const int row0 = blockIdx.x * 128;   // global (b,t) row
    const int b    = row0 >> 8;          // T=256 -> whole tile shares one b

    // ---- load + fused elementwise (gamma_x / x_hat), store transposed ----
    for (int idx = tid; idx < 128 * 128; idx += 256) {
        int r = idx >> 7, d = idx & 127;
        int g = (row0 + r) * DD + d;
        float xv = x[g], mv = mask[g], dl = delta[g], xl = xlast[g];
        float gx = __expf(-fmaxf(fmaf(w_dg_x[d], dl, b_dg_x[d]), 0.0f));
        float xm = x_mean[b * DD + d];
        float xh = mv * xv + (1.0f - mv) * (gx * xl + (1.0f - gx) * xm);
        As_x[d * APAD + r] = xh;   // pad-129 => stride-129 writes are conflict-free
        As_m[d * APAD + r] = mv;
        As_d[d * APAD + r] = dl;
    }
    __syncthreads();

    const int tx = tid & 15, ty = tid >> 4;
    const int r0 = ty * 8, j0 = tx * 8;
    float acc[8][8];

    // ---- gate Z ----
    #pragma unroll
    for (int i = 0; i < 8; i++)
        #pragma unroll
        for (int jj = 0; jj < 8; jj++) acc[i][jj] = b_z[j0 + jj];
    gemm_accum(As_x, g_WT + 0 * 16384, Bs, acc, tid, r0, j0);
    gemm_accum(As_m, g_WT + 1 * 16384, Bs, acc, tid, r0, j0);
    #pragma unroll
    for (int i = 0; i < 8; i++) {
        size_t g = (size_t)(row0 + r0 + i) * HH + j0;
        *(float4*)&g_Xz[g]     = make_float4(acc[i][0], acc[i][1], acc[i][2], acc[i][3]);
        *(float4*)&g_Xz[g + 4] = make_float4(acc[i][4], acc[i][5], acc[i][6], acc[i][7]);
    }

    // ---- gate R ----
    #pragma unroll
    for (int i = 0; i < 8; i++)
        #pragma unroll
        for (int jj = 0; jj < 8; jj++) acc[i][jj] = b_r[j0 + jj];
    gemm_accum(As_x, g_WT + 2 * 16384, Bs, acc, tid, r0, j0);
    gemm_accum(As_m, g_WT + 3 * 16384, Bs, acc, tid, r0, j0);
    #pragma unroll
    for (int i = 0; i < 8; i++) {
        size_t g = (size_t)(row0 + r0 + i) * HH + j0;
        *(float4*)&g_Xr[g]     = make_float4(acc[i][0], acc[i][1], acc[i][2], acc[i][3]);
        *(float4*)&g_Xr[g + 4] = make_float4(acc[i][4], acc[i][5], acc[i][6], acc[i][7]);
    }

    // ---- gate H ----
    #pragma unroll
    for (int i = 0; i < 8; i++)
        #pragma unroll
        for (int jj = 0; jj < 8; jj++) acc[i][jj] = b_h[j0 + jj];
    gemm_accum(As_x, g_WT + 4 * 16384, Bs, acc, tid, r0, j0);
    gemm_accum(As_m, g_WT + 5 * 16384, Bs, acc, tid, r0, j0);
    #pragma unroll
    for (int i = 0; i < 8; i++) {
        size_t g = (size_t)(row0 + r0 + i) * HH + j0;
        *(float4*)&g_Xh[g]     = make_float4(acc[i][0], acc[i][1], acc[i][2], acc[i][3]);
        *(float4*)&g_Xh[g + 4] = make_float4(acc[i][4], acc[i][5], acc[i][6], acc[i][7]);
    }

    // ---- gamma_h ----
    #pragma unroll
    for (int i = 0; i < 8; i++)
        #pragma unroll
        for (int jj = 0; jj < 8; jj++) acc[i][jj] = b_dg_h[j0 + jj];
    gemm_accum(As_d, g_WT + 6 * 16384, Bs, acc, tid, r0, j0);
    #pragma unroll
    for (int i = 0; i < 8; i++) {
        float v[8];
        #pragma unroll
        for (int jj = 0; jj < 8; jj++) v[jj] = __expf(-fmaxf(acc[i][jj], 0.0f));
        size_t g = (size_t)(row0 + r0 + i) * HH + j0;
        *(float4*)&g_gh[g]     = make_float4(v[0], v[1], v[2], v[3]);
        *(float4*)&g_gh[g + 4] = make_float4(v[4], v[5], v[6], v[7]);
    }
}

// ---------------------------------------------------------------------------
// Kernel 2: sequential recurrence. 128 CTAs x 4 batch rows, 128 threads.
// U_z/U_r/U_h transposed in smem (loaded once, reused 256 steps).
// Thread j owns hidden index j for all 4 rows; h published transposed
// as float4 per k for broadcast reads.
// ---------------------------------------------------------------------------
#define UPAD 129
#define U_SZ (128 * UPAD)

__global__ __launch_bounds__(128, 1)
void recurrent_kernel(const float* __restrict__ hs0,
                      const float* __restrict__ Uz, const float* __restrict__ Ur,
                      const float* __restrict__ Uh,
                      const float* __restrict__ statics,
                      const float* __restrict__ W_out, const float* __restrict__ b_out,
                      float* __restrict__ out)
{
    extern __shared__ float sm[];
    float* UzT = sm;
    float* UrT = sm + U_SZ;
    float* UhT = sm + 2 * U_SZ;
    float* hT  = sm + 3 * U_SZ;          // 128*4  (3*U_SZ = 49536 floats, 16B aligned)
    float* rhT = hT + 512;               // 128*4

    const int j  = threadIdx.x;          // hidden index owned by this thread
    const int b0 = blockIdx.x * 4;       // 4 batch rows per block

    // transpose-load U matrices: reads coalesced, writes stride-129 (conflict-free)
    for (int idx = j; idx < HH * HH; idx += 128) {
        int jj = idx >> 7, k = idx & 127;
        UzT[k * UPAD + jj] = Uz[idx];
        UrT[k * UPAD + jj] = Ur[idx];
        UhT[k * UPAD + jj] = Uh[idx];
    }

    float hreg[4];
    #pragma unroll
    for (int r = 0; r < 4; r++) hreg[r] = hs0[(b0 + r) * HH + j];

    // prefetch t=0 operands
    float cG[4], cXz[4], cXr[4], cXh[4];
    #pragma unroll
    for (int r = 0; r < 4; r++) {
        int g = ((b0 + r) * TT + 0) * HH + j;
        cG[r] = g_gh[g]; cXz[r] = g_Xz[g]; cXr[r] = g_Xr[g]; cXh[r] = g_Xh[g];
    }
    __syncthreads();

    for (int t = 0; t < TT; t++) {
        // h <- gamma_h * h ; publish transposed
        #pragma unroll
        for (int r = 0; r < 4; r++) hreg[r] *= cG[r];
        *(float4*)&hT[j * 4] = make_float4(hreg[0], hreg[1], hreg[2], hreg[3]);
        __syncthreads();

        // prefetch t+1 operands (hidden under the k-loops)
        float nG[4] = {0, 0, 0, 0}, nXz[4] = {0, 0, 0, 0},
              nXr[4] = {0, 0, 0, 0}, nXh[4] = {0, 0, 0, 0};
        if (t + 1 < TT) {
            #pragma unroll
            for (int r = 0; r < 4; r++) {
                int g = ((b0 + r) * TT + (t + 1)) * HH + j;
                nG[r] = g_gh[g]; nXz[r] = g_Xz[g]; nXr[r] = g_Xr[g]; nXh[r] = g_Xh[g];
            }
        }

        // z,r mat-vecs: acc_g[r] = sum_k h[r][k] * U_g[j][k]
        float accz[4] = {0, 0, 0, 0}, accr[4] = {0, 0, 0, 0};
        #pragma unroll 8
        for (int k = 0; k < 128; k++) {
            float4 hv = *(const float4*)&hT[k * 4];
            float uz = UzT[k * UPAD + j];
            float ur = UrT[k * UPAD + j];
            accz[0] = fmaf(hv.x, uz, accz[0]);
            accz[1] = fmaf(hv.y, uz, accz[1]);
            accz[2] = fmaf(hv.z, uz, accz[2]);
            accz[3] = fmaf(hv.w, uz, accz[3]);
            accr[0] = fmaf(hv.x, ur, accr[0]);
            accr[1] = fmaf(hv.y, ur, accr[1]);
            accr[2] = fmaf(hv.z, ur, accr[2]);
            accr[3] = fmaf(hv.w, ur, accr[3]);
        }

        float zg[4], rg[4];
        #pragma unroll
        for (int r = 0; r < 4; r++) {
            zg[r] = 1.0f / (1.0f + __expf(-(accz[r] + cXz[r])));
            rg[r] = 1.0f / (1.0f + __expf(-(accr[r] + cXr[r])));
        }

        // publish r*h transposed
        *(float4*)&rhT[j * 4] = make_float4(rg[0] * hreg[0], rg[1] * hreg[1],
                                            rg[2] * hreg[2], rg[3] * hreg[3]);
        __syncthreads();

        // h_tilde mat-vec
        float acch[4] = {0, 0, 0, 0};
        #pragma unroll 8
        for (int k = 0; k < 128; k++) {
            float4 rv = *(const float4*)&rhT[k * 4];
            float uh = UhT[k * UPAD + j];
            acch[0] = fmaf(rv.x, uh, acch[0]);
            acch[1] = fmaf(rv.y, uh, acch[1]);
            acch[2] = fmaf(rv.z, uh, acch[2]);
            acch[3] = fmaf(rv.w, uh, acch[3]);
        }

        #pragma unroll
        for (int r = 0; r < 4; r++) {
            float pre = acch[r] + cXh[r];
            float ht = 2.0f / (1.0f + __expf(-2.0f * pre)) - 1.0f;   // tanh
            hreg[r] = (1.0f - zg[r]) * hreg[r] + zg[r] * ht;
        }

        #pragma unroll
        for (int r = 0; r < 4; r++) {
            cG[r] = nG[r]; cXz[r] = nXz[r]; cXr[r] = nXr[r]; cXh[r] = nXh[r];
        }
    }

    // ---- classifier: pred[b] = h . W_out[0:128] + statics . W_out[128:160] + b_out
    __syncthreads();
    float wj = W_out[j];
    *(float4*)&hT[j * 4] = make_float4(hreg[0] * wj, hreg[1] * wj,
                                       hreg[2] * wj, hreg[3] * wj);
    __syncthreads();
    for (int s = 64; s > 0; s >>= 1) {
        if (j < s) {
            float4 a = *(const float4*)&hT[j * 4];
            float4 c = *(const float4*)&hT[(j + s) * 4];
            a.x += c.x; a.y += c.y; a.z += c.z; a.w += c.w;
            *(float4*)&hT[j * 4] = a;
        }
        __syncthreads();
    }
    if (j < 4) {
        float v = hT[j];     // component j of reduced float4 = row j sum
        float sacc = 0.0f;
        #pragma unroll
        for (int s = 0; s < SS; s++)
            sacc = fmaf(statics[(b0 + j) * SS + s], W_out[HH + s], sacc);
        out[b0 + j] = v + sacc + b_out[0];
    }
}

// ---------------------------------------------------------------------------
// Launch
// ---------------------------------------------------------------------------
extern "C" void kernel_launch(void* const* d_in, const int* in_sizes, int n_in,
                              void* d_out, int out_size)
{
    const float* x       = (const float*)d_in[0];
    const float* statics = (const float*)d_in[1];
    const float* mask    = (const float*)d_in[2];
    const float* delta   = (const float*)d_in[3];
    const float* xlast   = (const float*)d_in[4];
    const float* x_mean  = (const float*)d_in[5];
    const float* hs0     = (const float*)d_in[6];
    const float* w_dg_x  = (const float*)d_in[7];
    const float* b_dg_x  = (const float*)d_in[8];
    const float* W_dg_h  = (const float*)d_in[9];
    const float* b_dg_h  = (const float*)d_in[10];
    const float* W_z = (const float*)d_in[11];
    const float* U_z = (const float*)d_in[12];
    const float* V_z = (const float*)d_in[13];
    const float* b_z = (const float*)d_in[14];
    const float* W_r = (const float*)d_in[15];
    const float* U_r = (const float*)d_in[16];
    const float* V_r = (const float*)d_in[17];
    const float* b_r = (const float*)d_in[18];
    const float* W_h = (const float*)d_in[19];
    const float* U_h = (const float*)d_in[20];
    const float* V_h = (const float*)d_in[21];
    const float* b_h = (const float*)d_in[22];
    const float* W_out = (const float*)d_in[23];
    const float* b_out = (const float*)d_in[24];
    float* out = (float*)d_out;

    const int smemA = (3 * SMEM_A_SZ + 32 * 128) * (int)sizeof(float);   // 214528
    const int smemB = (3 * U_SZ + 1024) * (int)sizeof(float);            // 202240
    cudaFuncSetAttribute(precompute_kernel, cudaFuncAttributeMaxDynamicSharedMemorySize, smemA);
    cudaFuncSetAttribute(recurrent_kernel,  cudaFuncAttributeMaxDynamicSharedMemorySize, smemB);

    transpose_weights<<<7, 256>>>(W_z, V_z, W_r, V_r, W_h, V_h, W_dg_h);
    precompute_kernel<<<BT / 128, 256, smemA>>>(x, mask, delta, xlast, x_mean,
                                                w_dg_x, b_dg_x, b_dg_h, b_z, b_r, b_h);
    recurrent_kernel<<<BB / 4, 128, smemB>>>(hs0, U_z, U_r, U_h,
                                             statics, W_out, b_out, out);
}

// round 4
// speedup vs baseline: 1.0957x; 1.0957x over previous
#include <cuda_runtime.h>
#include <cstddef>

// Problem constants
#define BB 512
#define TT 256
#define DD 128
#define HH 128
#define SS 32
#define BT (BB*TT)   // 131072

typedef unsigned long long u64;

// ---------------------------------------------------------------------------
// f32x2 packed-math helpers (sm_103a FFMA2 path — only reachable via PTX)
// ---------------------------------------------------------------------------
__device__ __forceinline__ u64 ffma2(u64 a, u64 b, u64 c) {
    u64 d;
    asm("fma.rn.f32x2 %0, %1, %2, %3;" : "=l"(d) : "l"(a), "l"(b), "l"(c));
    return d;
}
__device__ __forceinline__ u64 pack2(float v) {
    u64 d;
    asm("mov.b64 %0, {%1, %1};" : "=l"(d) : "f"(v));
    return d;
}
__device__ __forceinline__ u64 packab(float a, float b) {
    u64 d;
    asm("mov.b64 %0, {%1, %2};" : "=l"(d) : "f"(a), "f"(b));
    return d;
}
__device__ __forceinline__ float2 unpk(u64 x) {
    float2 f;
    asm("mov.b64 {%0, %1}, %2;" : "=f"(f.x), "=f"(f.y) : "l"(x));
    return f;
}

union F4U2 { float4 f; u64 u[2]; };

// ---------------------------------------------------------------------------
// Device-global scratch (no cudaMalloc allowed)
// ---------------------------------------------------------------------------
__device__ float g_Xz[(size_t)BT * HH];   // 64 MiB each
__device__ float g_Xr[(size_t)BT * HH];
__device__ float g_Xh[(size_t)BT * HH];
__device__ float g_gh[(size_t)BT * HH];
__device__ float g_WT[7 * DD * HH];       // transposed weights [k][j]
// order: 0=WzT 1=VzT 2=WrT 3=VrT 4=WhT 5=VhT 6=WdghT

// ---------------------------------------------------------------------------
// Kernel 0: transpose the 7 input-projection weight matrices [j][k] -> [k][j]
// ---------------------------------------------------------------------------
__global__ void transpose_weights(const float* __restrict__ Wz, const float* __restrict__ Vz,
                                  const float* __restrict__ Wr, const float* __restrict__ Vr,
                                  const float* __restrict__ Wh, const float* __restrict__ Vh,
                                  const float* __restrict__ Wdgh)
{
    const float* srcs[7] = {Wz, Vz, Wr, Vr, Wh, Vh, Wdgh};
    const float* src = srcs[blockIdx.x];
    float* dst = g_WT + blockIdx.x * (DD * HH);
    for (int idx = threadIdx.x; idx < DD * HH; idx += blockDim.x) {
        int d = idx >> 7;
        int j = idx & 127;
        dst[idx] = src[j * DD + d];
    }
}

// ---------------------------------------------------------------------------
// Kernel 1: precompute. Block = 128 (b,t) rows x 128 cols, 256 threads,
// 8x8 per-thread tiles computed as 8x4 f32x2 accumulators.
//   Dup panel: A values stored duplicated {a,a} -> LDS.64 gives packed pair.
//   Mask panel: scalar; packs via MOV on the fly.
// ---------------------------------------------------------------------------
#define PD 258                     // dup panel pitch (floats): 2*128+2
#define PM 129                     // mask panel pitch
#define ADUP_SZ (128 * PD)         // 33024 floats
#define AM_SZ   (128 * PM)         // 16512 floats

// dup-path GEMM: acc2[i][jc] += {a,a} * {b0,b1}
__device__ __forceinline__ void gemm_dup(const float* __restrict__ Ad,
                                         const float* __restrict__ WT,
                                         float* __restrict__ Bs,
                                         u64 acc[8][4],
                                         int tid, int r0, int j0)
{
    #pragma unroll 1
    for (int kt = 0; kt < 4; kt++) {
        for (int idx = tid; idx < 32 * 128; idx += 256)
            Bs[idx] = WT[kt * 32 * 128 + idx];
        __syncthreads();
        #pragma unroll
        for (int d = 0; d < 32; d++) {
            u64 a2[8];
            const int base = (kt * 32 + d) * PD;   // even -> 8B aligned
            #pragma unroll
            for (int i = 0; i < 8; i++)
                a2[i] = *(const u64*)&Ad[base + 2 * (r0 + i)];
            F4U2 b0, b1;
            b0.f = *(const float4*)&Bs[d * 128 + j0];
            b1.f = *(const float4*)&Bs[d * 128 + j0 + 4];
            u64 bv[4] = {b0.u[0], b0.u[1], b1.u[0], b1.u[1]};
            #pragma unroll
            for (int i = 0; i < 8; i++)
                #pragma unroll
                for (int jc = 0; jc < 4; jc++)
                    acc[i][jc] = ffma2(a2[i], bv[jc], acc[i][jc]);
        }
        __syncthreads();
    }
}

// scalar-A path GEMM (mask panel): pack {a,a} with MOV
__device__ __forceinline__ void gemm_pk(const float* __restrict__ Am,
                                        const float* __restrict__ WT,
                                        float* __restrict__ Bs,
                                        u64 acc[8][4],
                                        int tid, int r0, int j0)
{
    #pragma unroll 1
    for (int kt = 0; kt < 4; kt++) {
        for (int idx = tid; idx < 32 * 128; idx += 256)
            Bs[idx] = WT[kt * 32 * 128 + idx];
        __syncthreads();
        #pragma unroll
        for (int d = 0; d < 32; d++) {
            const float* arow = &Am[(kt * 32 + d) * PM + r0];
            u64 a2[8];
            #pragma unroll
            for (int i = 0; i < 8; i++) a2[i] = pack2(arow[i]);
            F4U2 b0, b1;
            b0.f = *(const float4*)&Bs[d * 128 + j0];
            b1.f = *(const float4*)&Bs[d * 128 + j0 + 4];
            u64 bv[4] = {b0.u[0], b0.u[1], b1.u[0], b1.u[1]};
            #pragma unroll
            for (int i = 0; i < 8; i++)
                #pragma unroll
                for (int jc = 0; jc < 4; jc++)
                    acc[i][jc] = ffma2(a2[i], bv[jc], acc[i][jc]);
        }
        __syncthreads();
    }
}

__global__ __launch_bounds__(256, 1)
void precompute_kernel(const float* __restrict__ x,     const float* __restrict__ mask,
                       const float* __restrict__ delta, const float* __restrict__ xlast,
                       const float* __restrict__ x_mean,
                       const float* __restrict__ w_dg_x, const float* __restrict__ b_dg_x,
                       const float* __restrict__ b_dg_h,
                       const float* __restrict__ b_z, const float* __restrict__ b_r,
                       const float* __restrict__ b_h)
{
    extern __shared__ float sm[];
    float* Adup = sm;                    // 33024 floats (129 KB)
    float* Am   = sm + ADUP_SZ;          // 16512 floats (64.5 KB)
    float* Bs   = sm + ADUP_SZ + AM_SZ;  // 4096 floats (16 KB)

    const int tid  = threadIdx.x;
    const int row0 = blockIdx.x * 128;   // global (b,t) row
    const int b    = row0 >> 8;          // T=256: whole tile shares one b

    const int tx = tid & 15, ty = tid >> 4;
    const int r0 = ty * 8, j0 = tx * 8;

    // ---- pass 1: delta -> dup panel, mask -> scalar panel ----
    for (int idx = tid; idx < 128 * 128; idx += 256) {
        int r = idx >> 7, d = idx & 127;
        int g = (row0 + r) * DD + d;
        float dl = delta[g], mv = mask[g];
        *(u64*)&Adup[d * PD + 2 * r] = pack2(dl);
        Am[d * PM + r] = mv;
    }
    __syncthreads();

    u64 acc[8][4];

    // ---- gamma_h = exp(-relu(delta @ Wdgh.T + b_dgh)) ----
    #pragma unroll
    for (int i = 0; i < 8; i++)
        #pragma unroll
        for (int jc = 0; jc < 4; jc++)
            acc[i][jc] = *(const u64*)&b_dg_h[j0 + 2 * jc];
    gemm_dup(Adup, g_WT + 6 * 16384, Bs, acc, tid, r0, j0);
    #pragma unroll
    for (int i = 0; i < 8; i++) {
        F4U2 o0, o1;
        #pragma unroll
        for (int jc = 0; jc < 4; jc++) {
            float2 v = unpk(acc[i][jc]);
            v.x = __expf(-fmaxf(v.x, 0.0f));
            v.y = __expf(-fmaxf(v.y, 0.0f));
            if (jc < 2) o0.u[jc] = packab(v.x, v.y);
            else        o1.u[jc - 2] = packab(v.x, v.y);
        }
        size_t g = (size_t)(row0 + r0 + i) * HH + j0;
        *(float4*)&g_gh[g]     = o0.f;
        *(float4*)&g_gh[g + 4] = o1.f;
    }
    __syncthreads();   // all reads of Adup(delta) done

    // ---- pass 2: x_hat -> dup panel (mask read back from smem) ----
    for (int idx = tid; idx < 128 * 128; idx += 256) {
        int r = idx >> 7, d = idx & 127;
        int g = (row0 + r) * DD + d;
        float xv = x[g], dl = delta[g], xl = xlast[g];
        float mv = Am[d * PM + r];
        float gx = __expf(-fmaxf(fmaf(w_dg_x[d], dl, b_dg_x[d]), 0.0f));
        float xm = x_mean[b * DD + d];
        float xh = mv * xv + (1.0f - mv) * (gx * xl + (1.0f - gx) * xm);
        *(u64*)&Adup[d * PD + 2 * r] = pack2(xh);
    }
    __syncthreads();

    // ---- gate Z ----
    #pragma unroll
    for (int i = 0; i < 8; i++)
        #pragma unroll
        for (int jc = 0; jc < 4; jc++)
            acc[i][jc] = *(const u64*)&b_z[j0 + 2 * jc];
    gemm_dup(Adup, g_WT + 0 * 16384, Bs, acc, tid, r0, j0);
    gemm_pk (Am,   g_WT + 1 * 16384, Bs, acc, tid, r0, j0);
    #pragma unroll
    for (int i = 0; i < 8; i++) {
        F4U2 o0, o1;
        o0.u[0] = acc[i][0]; o0.u[1] = acc[i][1];
        o1.u[0] = acc[i][2]; o1.u[1] = acc[i][3];
        size_t g = (size_t)(row0 + r0 + i) * HH + j0;
        *(float4*)&g_Xz[g]     = o0.f;
        *(float4*)&g_Xz[g + 4] = o1.f;
    }

    // ---- gate R ----
    #pragma unroll
    for (int i = 0; i < 8; i++)
        #pragma unroll
        for (int jc = 0; jc < 4; jc++)
            acc[i][jc] = *(const u64*)&b_r[j0 + 2 * jc];
    gemm_dup(Adup, g_WT + 2 * 16384, Bs, acc, tid, r0, j0);
    gemm_pk (Am,   g_WT + 3 * 16384, Bs, acc, tid, r0, j0);
    #pragma unroll
    for (int i = 0; i < 8; i++) {
        F4U2 o0, o1;
        o0.u[0] = acc[i][0]; o0.u[1] = acc[i][1];
        o1.u[0] = acc[i][2]; o1.u[1] = acc[i][3];
        size_t g = (size_t)(row0 + r0 + i) * HH + j0;
        *(float4*)&g_Xr[g]     = o0.f;
        *(float4*)&g_Xr[g + 4] = o1.f;
    }

    // ---- gate H ----
    #pragma unroll
    for (int i = 0; i < 8; i++)
        #pragma unroll
        for (int jc = 0; jc < 4; jc++)
            acc[i][jc] = *(const u64*)&b_h[j0 + 2 * jc];
    gemm_dup(Adup, g_WT + 4 * 16384, Bs, acc, tid, r0, j0);
    gemm_pk (Am,   g_WT + 5 * 16384, Bs, acc, tid, r0, j0);
    #pragma unroll
    for (int i = 0; i < 8; i++) {
        F4U2 o0, o1;
        o0.u[0] = acc[i][0]; o0.u[1] = acc[i][1];
        o1.u[0] = acc[i][2]; o1.u[1] = acc[i][3];
        size_t g = (size_t)(row0 + r0 + i) * HH + j0;
        *(float4*)&g_Xh[g]     = o0.f;
        *(float4*)&g_Xh[g + 4] = o1.f;
    }
}

// ---------------------------------------------------------------------------
// Kernel 2: sequential recurrence. 128 CTAs x 4 batch rows, 128 threads.
// Uz/Ur interleaved per k (one LDS.64 -> both), f32x2 row-pair FMAs.
// ---------------------------------------------------------------------------
#define PZR 258                    // [k][2j..2j+1] = {uz, ur}, pitch 258
#define PUH 129
#define UZR_SZ (128 * PZR)         // 33024 floats
#define UH_SZ  (128 * PUH)         // 16512 floats

__global__ __launch_bounds__(128, 1)
void recurrent_kernel(const float* __restrict__ hs0,
                      const float* __restrict__ Uz, const float* __restrict__ Ur,
                      const float* __restrict__ Uh,
                      const float* __restrict__ statics,
                      const float* __restrict__ W_out, const float* __restrict__ b_out,
                      float* __restrict__ out)
{
    extern __shared__ float sm[];
    float* UzrT = sm;                    // 33024
    float* UhT  = sm + UZR_SZ;           // 16512
    float* hT   = sm + UZR_SZ + UH_SZ;   // 512
    float* rhT  = hT + 512;              // 512

    const int j  = threadIdx.x;
    const int b0 = blockIdx.x * 4;

    // transpose-load: coalesced global reads; UzrT interleaved per k
    for (int idx = j; idx < HH * HH; idx += 128) {
        int jj = idx >> 7, k = idx & 127;
        UzrT[k * PZR + 2 * jj]     = Uz[idx];
        UzrT[k * PZR + 2 * jj + 1] = Ur[idx];
        UhT[k * PUH + jj]          = Uh[idx];
    }

    float hreg[4];
    #pragma unroll
    for (int r = 0; r < 4; r++) hreg[r] = hs0[(b0 + r) * HH + j];

    float cG[4], cXz[4], cXr[4], cXh[4];
    #pragma unroll
    for (int r = 0; r < 4; r++) {
        int g = ((b0 + r) * TT + 0) * HH + j;
        cG[r] = g_gh[g]; cXz[r] = g_Xz[g]; cXr[r] = g_Xr[g]; cXh[r] = g_Xh[g];
    }
    __syncthreads();

    for (int t = 0; t < TT; t++) {
        #pragma unroll
        for (int r = 0; r < 4; r++) hreg[r] *= cG[r];
        *(float4*)&hT[j * 4] = make_float4(hreg[0], hreg[1], hreg[2], hreg[3]);
        __syncthreads();

        // prefetch t+1 operands (land under the k-loops)
        float nG[4] = {0, 0, 0, 0}, nXz[4] = {0, 0, 0, 0},
              nXr[4] = {0, 0, 0, 0}, nXh[4] = {0, 0, 0, 0};
        if (t + 1 < TT) {
            #pragma unroll
            for (int r = 0; r < 4; r++) {
                int g = ((b0 + r) * TT + (t + 1)) * HH + j;
                nG[r] = g_gh[g]; nXz[r] = g_Xz[g]; nXr[r] = g_Xr[g]; nXh[r] = g_Xh[g];
            }
        }

        // z,r mat-vecs in f32x2: rows (0,1) and (2,3) packed
        u64 az01 = 0, az23 = 0, ar01 = 0, ar23 = 0;
        #pragma unroll 8
        for (int k = 0; k < 128; k++) {
            F4U2 hv; hv.f = *(const float4*)&hT[k * 4];
            float2 uu = *(const float2*)&UzrT[k * PZR + 2 * j];
            u64 uz2 = pack2(uu.x), ur2 = pack2(uu.y);
            az01 = ffma2(hv.u[0], uz2, az01);
            az23 = ffma2(hv.u[1], uz2, az23);
            ar01 = ffma2(hv.u[0], ur2, ar01);
            ar23 = ffma2(hv.u[1], ur2, ar23);
        }
        float2 z01 = unpk(az01), z23 = unpk(az23);
        float2 r01 = unpk(ar01), r23 = unpk(ar23);
        float accz[4] = {z01.x, z01.y, z23.x, z23.y};
        float accr[4] = {r01.x, r01.y, r23.x, r23.y};

        float zg[4], rg[4];
        #pragma unroll
        for (int r = 0; r < 4; r++) {
            zg[r] = 1.0f / (1.0f + __expf(-(accz[r] + cXz[r])));
            rg[r] = 1.0f / (1.0f + __expf(-(accr[r] + cXr[r])));
        }

        *(float4*)&rhT[j * 4] = make_float4(rg[0] * hreg[0], rg[1] * hreg[1],
                                            rg[2] * hreg[2], rg[3] * hreg[3]);
        __syncthreads();

        // h_tilde mat-vec in f32x2
        u64 ah01 = 0, ah23 = 0;
        #pragma unroll 8
        for (int k = 0; k < 128; k++) {
            F4U2 rv; rv.f = *(const float4*)&rhT[k * 4];
            u64 uh2 = pack2(UhT[k * PUH + j]);
            ah01 = ffma2(rv.u[0], uh2, ah01);
            ah23 = ffma2(rv.u[1], uh2, ah23);
        }
        float2 h01 = unpk(ah01), h23 = unpk(ah23);
        float acch[4] = {h01.x, h01.y, h23.x, h23.y};

        #pragma unroll
        for (int r = 0; r < 4; r++) {
            float pre = acch[r] + cXh[r];
            float ht = 2.0f / (1.0f + __expf(-2.0f * pre)) - 1.0f;   // tanh
            hreg[r] = (1.0f - zg[r]) * hreg[r] + zg[r] * ht;
        }

        #pragma unroll
        for (int r = 0; r < 4; r++) {
            cG[r] = nG[r]; cXz[r] = nXz[r]; cXr[r] = nXr[r]; cXh[r] = nXh[r];
        }
    }

    // ---- classifier ----
    __syncthreads();
    float wj = W_out[j];
    *(float4*)&hT[j * 4] = make_float4(hreg[0] * wj, hreg[1] * wj,
                                       hreg[2] * wj, hreg[3] * wj);
    __syncthreads();
    for (int s = 64; s > 0; s >>= 1) {
        if (j < s) {
            float4 a = *(const float4*)&hT[j * 4];
            float4 c = *(const float4*)&hT[(j + s) * 4];
            a.x += c.x; a.y += c.y; a.z += c.z; a.w += c.w;
            *(float4*)&hT[j * 4] = a;
        }
        __syncthreads();
    }
    if (j < 4) {
        float v = hT[j];
        float sacc = 0.0f;
        #pragma unroll
        for (int s = 0; s < SS; s++)
            sacc = fmaf(statics[(b0 + j) * SS + s], W_out[HH + s], sacc);
        out[b0 + j] = v + sacc + b_out[0];
    }
}

// ---------------------------------------------------------------------------
// Launch
// ---------------------------------------------------------------------------
extern "C" void kernel_launch(void* const* d_in, const int* in_sizes, int n_in,
                              void* d_out, int out_size)
{
    const float* x       = (const float*)d_in[0];
    const float* statics = (const float*)d_in[1];
    const float* mask    = (const float*)d_in[2];
    const float* delta   = (const float*)d_in[3];
    const float* xlast   = (const float*)d_in[4];
    const float* x_mean  = (const float*)d_in[5];
    const float* hs0     = (const float*)d_in[6];
    const float* w_dg_x  = (const float*)d_in[7];
    const float* b_dg_x  = (const float*)d_in[8];
    const float* W_dg_h  = (const float*)d_in[9];
    const float* b_dg_h  = (const float*)d_in[10];
    const float* W_z = (const float*)d_in[11];
    const float* U_z = (const float*)d_in[12];
    const float* V_z = (const float*)d_in[13];
    const float* b_z = (const float*)d_in[14];
    const float* W_r = (const float*)d_in[15];
    const float* U_r = (const float*)d_in[16];
    const float* V_r = (const float*)d_in[17];
    const float* b_r = (const float*)d_in[18];
    const float* W_h = (const float*)d_in[19];
    const float* U_h = (const float*)d_in[20];
    const float* V_h = (const float*)d_in[21];
    const float* b_h = (const float*)d_in[22];
    const float* W_out = (const float*)d_in[23];
    const float* b_out = (const float*)d_in[24];
    float* out = (float*)d_out;

    const int smemA = (ADUP_SZ + AM_SZ + 32 * 128) * (int)sizeof(float);  // 214528
    const int smemB = (UZR_SZ + UH_SZ + 1024) * (int)sizeof(float);      // 202240
    cudaFuncSetAttribute(precompute_kernel, cudaFuncAttributeMaxDynamicSharedMemorySize, smemA);
    cudaFuncSetAttribute(recurrent_kernel,  cudaFuncAttributeMaxDynamicSharedMemorySize, smemB);

    transpose_weights<<<7, 256>>>(W_z, V_z, W_r, V_r, W_h, V_h, W_dg_h);
    precompute_kernel<<<BT / 128, 256, smemA>>>(x, mask, delta, xlast, x_mean,
                                                w_dg_x, b_dg_x, b_dg_h, b_z, b_r, b_h);
    recurrent_kernel<<<BB / 4, 128, smemB>>>(hs0, U_z, U_r, U_h,
                                             statics, W_out, b_out, out);
}

// round 6
// speedup vs baseline: 1.5513x; 1.4158x over previous
#include <cuda_runtime.h>
#include <cuda_bf16.h>
#include <cstddef>
#include <cstdint>

// Problem constants
#define BB 512
#define TT 256
#define DD 128
#define HH 128
#define SS 32
#define BT (BB*TT)   // 131072

typedef unsigned long long u64;
typedef uint32_t u32;

// ---------------------------------------------------------------------------
// f32x2 packed-math helpers (recurrence kernel)
// ---------------------------------------------------------------------------
__device__ __forceinline__ u64 ffma2(u64 a, u64 b, u64 c) {
    u64 d;
    asm("fma.rn.f32x2 %0, %1, %2, %3;" : "=l"(d) : "l"(a), "l"(b), "l"(c));
    return d;
}
__device__ __forceinline__ u64 pack2(float v) {
    u64 d;
    asm("mov.b64 %0, {%1, %1};" : "=l"(d) : "f"(v));
    return d;
}
__device__ __forceinline__ float2 unpk(u64 x) {
    float2 f;
    asm("mov.b64 {%0, %1}, %2;" : "=f"(f.x), "=f"(f.y) : "l"(x));
    return f;
}
union F4U2 { float4 f; u64 u[2]; };

// ---------------------------------------------------------------------------
// Device-global scratch
// ---------------------------------------------------------------------------
__device__ float g_Xz[(size_t)BT * HH];
__device__ float g_Xr[(size_t)BT * HH];
__device__ float g_Xh[(size_t)BT * HH];
__device__ float g_gh[(size_t)BT * HH];
// bf16 hi/lo weight copies, layout [j][d] (native), order:
// 0=W_z 1=V_z 2=W_r 3=V_r 4=W_h 5=V_h 6=W_dg_h
__device__ __nv_bfloat16 g_Wbh[7 * 16384];
__device__ __nv_bfloat16 g_Wbl[7 * 16384];

__global__ void noop_kernel() {}

// ---------------------------------------------------------------------------
// Kernel 0: convert 7 weight matrices fp32 -> bf16 hi/lo (same [j][d] layout)
// ---------------------------------------------------------------------------
__global__ void convert_w(const float* __restrict__ Wz, const float* __restrict__ Vz,
                          const float* __restrict__ Wr, const float* __restrict__ Vr,
                          const float* __restrict__ Wh, const float* __restrict__ Vh,
                          const float* __restrict__ Wdgh)
{
    const float* srcs[7] = {Wz, Vz, Wr, Vr, Wh, Vh, Wdgh};
    const float* s = srcs[blockIdx.x];
    __nv_bfloat16* dh = g_Wbh + blockIdx.x * 16384;
    __nv_bfloat16* dl = g_Wbl + blockIdx.x * 16384;
    for (int idx = threadIdx.x; idx < 16384; idx += blockDim.x) {
        float v = s[idx];
        __nv_bfloat16 h = __float2bfloat16(v);
        dh[idx] = h;
        dl[idx] = __float2bfloat16(v - __bfloat162float(h));
    }
}

// ---------------------------------------------------------------------------
// Kernel 1: precompute via warp-level mma.sync (HMMA bf16, fp32 accum).
// 1024 blocks x 256 threads (8 warps). Warp w owns rows w*16..w*16+15.
// Panels in smem, pitch 136 bf16 (conflict-free u32 fragment loads).
// ---------------------------------------------------------------------------
#define PA 136                                   // bf16 per smem row
#define PANEL_B (128 * PA * 2)                   // 34816 bytes
#define SM_BIAS  0                               // 128 fp32 = 512 B
#define SM_AHI   512
#define SM_ALO   (SM_AHI + PANEL_B)
#define SM_MBF   (SM_ALO + PANEL_B)
#define SM_WHI   (SM_MBF + PANEL_B)
#define SM_WLO   (SM_WHI + PANEL_B)
#define SM_TOTAL (SM_WLO + PANEL_B)              // 174592 bytes

__device__ __forceinline__ void mma_bf16(float c[4], u32 a0, u32 a1, u32 a2, u32 a3,
                                         u32 b0, u32 b1) {
    asm("mma.sync.aligned.m16n8k16.row.col.f32.bf16.bf16.f32 "
        "{%0,%1,%2,%3}, {%4,%5,%6,%7}, {%8,%9}, {%0,%1,%2,%3};"
        : "+f"(c[0]), "+f"(c[1]), "+f"(c[2]), "+f"(c[3])
        : "r"(a0), "r"(a1), "r"(a2), "r"(a3), "r"(b0), "r"(b1));
}

// one 128x128x128 pass: acc[nt][4] += A(rows row0..row0+15) @ W^T
__device__ __forceinline__ void gpass(const __nv_bfloat16* __restrict__ A,
                                      const __nv_bfloat16* __restrict__ W,
                                      float acc[16][4], int row0, int lane)
{
    const int g = lane >> 2, t = lane & 3;
    #pragma unroll
    for (int kt = 0; kt < 8; kt++) {
        const __nv_bfloat16* ap = A + (row0 + g) * PA + kt * 16 + 2 * t;
        u32 a0 = *(const u32*)ap;
        u32 a1 = *(const u32*)(ap + 8 * PA);
        u32 a2 = *(const u32*)(ap + 8);
        u32 a3 = *(const u32*)(ap + 8 * PA + 8);
        #pragma unroll
        for (int nt = 0; nt < 16; nt++) {
            const __nv_bfloat16* bp = W + (nt * 8 + g) * PA + kt * 16 + 2 * t;
            u32 b0 = *(const u32*)bp;
            u32 b1 = *(const u32*)(bp + 8);
            mma_bf16(acc[nt], a0, a1, a2, a3, b0, b1);
        }
    }
}

// stage one 128x128 bf16 weight matrix (row-major [j][k]) into padded smem
__device__ __forceinline__ void stage_w(char* smem, int off, const __nv_bfloat16* g) {
    const uint4* src = (const uint4*)g;   // 8 bf16 per uint4, 2048 chunks
    #pragma unroll
    for (int it = 0; it < 8; it++) {
        int cc = threadIdx.x + it * 256;
        int j = cc >> 4, k8 = (cc & 15) * 8;
        *(uint4*)(smem + off + (j * PA + k8) * 2) = src[cc];
    }
}

__global__ __launch_bounds__(256, 1)
void precompute_mma(const float* __restrict__ x,     const float* __restrict__ mask,
                    const float* __restrict__ delta, const float* __restrict__ xlast,
                    const float* __restrict__ x_mean,
                    const float* __restrict__ w_dg_x, const float* __restrict__ b_dg_x,
                    const float* __restrict__ b_dg_h,
                    const float* __restrict__ b_z, const float* __restrict__ b_r,
                    const float* __restrict__ b_h)
{
    extern __shared__ char smem[];
    float* bias_s = (float*)(smem + SM_BIAS);
    __nv_bfloat16* Ahi = (__nv_bfloat16*)(smem + SM_AHI);
    __nv_bfloat16* Alo = (__nv_bfloat16*)(smem + SM_ALO);
    __nv_bfloat16* Mbf = (__nv_bfloat16*)(smem + SM_MBF);
    __nv_bfloat16* Whi = (__nv_bfloat16*)(smem + SM_WHI);
    __nv_bfloat16* Wlo = (__nv_bfloat16*)(smem + SM_WLO);

    const int tid  = threadIdx.x;
    const int lane = tid & 31;
    const int wrp  = tid >> 5;
    const int row0 = wrp * 16;           // warp's row slice within the tile
    const int brow = blockIdx.x * 128;   // global (b,t) row of tile
    const int b    = brow >> 8;
    const int g = lane >> 2, t = lane & 3;

    float acc[16][4];

    // ---- pass 1 panels: delta hi/lo ----
    for (int idx = tid; idx < 128 * 128; idx += 256) {
        int r = idx >> 7, d = idx & 127;
        float v = delta[(size_t)(brow + r) * DD + d];
        __nv_bfloat16 hi = __float2bfloat16(v);
        Ahi[r * PA + d] = hi;
        Alo[r * PA + d] = __float2bfloat16(v - __bfloat162float(hi));
    }
    stage_w(smem, SM_WHI, g_Wbh + 6 * 16384);
    stage_w(smem, SM_WLO, g_Wbl + 6 * 16384);
    if (tid < 128) bias_s[tid] = b_dg_h[tid];
    __syncthreads();

    // ---- gamma_h = exp(-relu(delta @ Wdgh.T + b_dgh)) ----
    #pragma unroll
    for (int nt = 0; nt < 16; nt++)
        #pragma unroll
        for (int q = 0; q < 4; q++) acc[nt][q] = 0.0f;
    {
        const __nv_bfloat16* Ap[3] = {Ahi, Ahi, Alo};
        const __nv_bfloat16* Wp[3] = {Whi, Wlo, Whi};
        #pragma unroll 1
        for (int p = 0; p < 3; p++)
            gpass(Ap[p], Wp[p], acc, row0, lane);
    }
    #pragma unroll
    for (int nt = 0; nt < 16; nt++) {
        int j0 = nt * 8 + 2 * t;
        float b0v = bias_s[j0], b1v = bias_s[j0 + 1];
        size_t r0g = (size_t)(brow + row0 + g) * HH + j0;
        size_t r8g = (size_t)(brow + row0 + g + 8) * HH + j0;
        *(float2*)&g_gh[r0g] = make_float2(__expf(-fmaxf(acc[nt][0] + b0v, 0.0f)),
                                           __expf(-fmaxf(acc[nt][1] + b1v, 0.0f)));
        *(float2*)&g_gh[r8g] = make_float2(__expf(-fmaxf(acc[nt][2] + b0v, 0.0f)),
                                           __expf(-fmaxf(acc[nt][3] + b1v, 0.0f)));
    }
    __syncthreads();   // all gpass reads of delta panels done

    // ---- pass 2 panels: x_hat hi/lo, mask ----
    for (int idx = tid; idx < 128 * 128; idx += 256) {
        int r = idx >> 7, d = idx & 127;
        size_t gg = (size_t)(brow + r) * DD + d;
        float xv = x[gg], mv = mask[gg], dl = delta[gg], xl = xlast[gg];
        float gx = __expf(-fmaxf(fmaf(w_dg_x[d], dl, b_dg_x[d]), 0.0f));
        float xm = x_mean[b * DD + d];
        float xh = mv * xv + (1.0f - mv) * (gx * xl + (1.0f - gx) * xm);
        __nv_bfloat16 hi = __float2bfloat16(xh);
        Ahi[r * PA + d] = hi;
        Alo[r * PA + d] = __float2bfloat16(xh - __bfloat162float(hi));
        Mbf[r * PA + d] = __float2bfloat16(mv);   // 0/1 exact
    }
    __syncthreads();

    // ---- gates z, r, h ----
    const int wi[3] = {0, 2, 4};
    const int vi[3] = {1, 3, 5};
    const float* biases[3] = {b_z, b_r, b_h};
    float* outs[3] = {g_Xz, g_Xr, g_Xh};

    #pragma unroll 1
    for (int gate = 0; gate < 3; gate++) {
        stage_w(smem, SM_WHI, g_Wbh + wi[gate] * 16384);
        stage_w(smem, SM_WLO, g_Wbl + wi[gate] * 16384);
        if (tid < 128) bias_s[tid] = biases[gate][tid];
        __syncthreads();

        #pragma unroll
        for (int nt = 0; nt < 16; nt++)
            #pragma unroll
            for (int q = 0; q < 4; q++) acc[nt][q] = 0.0f;

        const __nv_bfloat16* Ap[5] = {Ahi, Ahi, Alo, Mbf, Mbf};
        const __nv_bfloat16* Wp[5] = {Whi, Wlo, Whi, Whi, Wlo};
        #pragma unroll 1
        for (int p = 0; p < 5; p++) {
            if (p == 3) {
                __syncthreads();   // W reads done
                stage_w(smem, SM_WHI, g_Wbh + vi[gate] * 16384);
                stage_w(smem, SM_WLO, g_Wbl + vi[gate] * 16384);
                __syncthreads();
            }
            gpass(Ap[p], Wp[p], acc, row0, lane);
        }

        float* obase = outs[gate];
        #pragma unroll
        for (int nt = 0; nt < 16; nt++) {
            int j0 = nt * 8 + 2 * t;
            float b0v = bias_s[j0], b1v = bias_s[j0 + 1];
            size_t r0g = (size_t)(brow + row0 + g) * HH + j0;
            size_t r8g = (size_t)(brow + row0 + g + 8) * HH + j0;
            *(float2*)&obase[r0g] = make_float2(acc[nt][0] + b0v, acc[nt][1] + b1v);
            *(float2*)&obase[r8g] = make_float2(acc[nt][2] + b0v, acc[nt][3] + b1v);
        }
        __syncthreads();   // epilogue/bias reads done before next gate stages
    }
}

// ---------------------------------------------------------------------------
// Kernel 2: sequential recurrence (f32x2)
// ---------------------------------------------------------------------------
#define PZR 258
#define PUH 129
#define UZR_SZ (128 * PZR)
#define UH_SZ  (128 * PUH)

__global__ __launch_bounds__(128, 1)
void recurrent_kernel(const float* __restrict__ hs0,
                      const float* __restrict__ Uz, const float* __restrict__ Ur,
                      const float* __restrict__ Uh,
                      const float* __restrict__ statics,
                      const float* __restrict__ W_out, const float* __restrict__ b_out,
                      float* __restrict__ out)
{
    extern __shared__ float sm[];
    float* UzrT = sm;
    float* UhT  = sm + UZR_SZ;
    float* hT   = sm + UZR_SZ + UH_SZ;
    float* rhT  = hT + 512;

    const int j  = threadIdx.x;
    const int b0 = blockIdx.x * 4;

    for (int idx = j; idx < HH * HH; idx += 128) {
        int jj = idx >> 7, k = idx & 127;
        UzrT[k * PZR + 2 * jj]     = Uz[idx];
        UzrT[k * PZR + 2 * jj + 1] = Ur[idx];
        UhT[k * PUH + jj]          = Uh[idx];
    }

    float hreg[4];
    #pragma unroll
    for (int r = 0; r < 4; r++) hreg[r] = hs0[(b0 + r) * HH + j];

    float cG[4], cXz[4], cXr[4], cXh[4];
    #pragma unroll
    for (int r = 0; r < 4; r++) {
        int g = ((b0 + r) * TT + 0) * HH + j;
        cG[r] = g_gh[g]; cXz[r] = g_Xz[g]; cXr[r] = g_Xr[g]; cXh[r] = g_Xh[g];
    }
    __syncthreads();

    for (int t = 0; t < TT; t++) {
        #pragma unroll
        for (int r = 0; r < 4; r++) hreg[r] *= cG[r];
        *(float4*)&hT[j * 4] = make_float4(hreg[0], hreg[1], hreg[2], hreg[3]);
        __syncthreads();

        float nG[4] = {0, 0, 0, 0}, nXz[4] = {0, 0, 0, 0},
              nXr[4] = {0, 0, 0, 0}, nXh[4] = {0, 0, 0, 0};
        if (t + 1 < TT) {
            #pragma unroll
            for (int r = 0; r < 4; r++) {
                int g = ((b0 + r) * TT + (t + 1)) * HH + j;
                nG[r] = g_gh[g]; nXz[r] = g_Xz[g]; nXr[r] = g_Xr[g]; nXh[r] = g_Xh[g];
            }
        }

        u64 az01 = 0, az23 = 0, ar01 = 0, ar23 = 0;
        #pragma unroll 8
        for (int k = 0; k < 128; k++) {
            F4U2 hv; hv.f = *(const float4*)&hT[k * 4];
            float2 uu = *(const float2*)&UzrT[k * PZR + 2 * j];
            u64 uz2 = pack2(uu.x), ur2 = pack2(uu.y);
            az01 = ffma2(hv.u[0], uz2, az01);
            az23 = ffma2(hv.u[1], uz2, az23);
            ar01 = ffma2(hv.u[0], ur2, ar01);
            ar23 = ffma2(hv.u[1], ur2, ar23);
        }
        float2 z01 = unpk(az01), z23 = unpk(az23);
        float2 r01 = unpk(ar01), r23 = unpk(ar23);
        float accz[4] = {z01.x, z01.y, z23.x, z23.y};
        float accr[4] = {r01.x, r01.y, r23.x, r23.y};

        float zg[4], rg[4];
        #pragma unroll
        for (int r = 0; r < 4; r++) {
            zg[r] = 1.0f / (1.0f + __expf(-(accz[r] + cXz[r])));
            rg[r] = 1.0f / (1.0f + __expf(-(accr[r] + cXr[r])));
        }

        *(float4*)&rhT[j * 4] = make_float4(rg[0] * hreg[0], rg[1] * hreg[1],
                                            rg[2] * hreg[2], rg[3] * hreg[3]);
        __syncthreads();

        u64 ah01 = 0, ah23 = 0;
        #pragma unroll 8
        for (int k = 0; k < 128; k++) {
            F4U2 rv; rv.f = *(const float4*)&rhT[k * 4];
            u64 uh2 = pack2(UhT[k * PUH + j]);
            ah01 = ffma2(rv.u[0], uh2, ah01);
            ah23 = ffma2(rv.u[1], uh2, ah23);
        }
        float2 h01 = unpk(ah01), h23 = unpk(ah23);
        float acch[4] = {h01.x, h01.y, h23.x, h23.y};

        #pragma unroll
        for (int r = 0; r < 4; r++) {
            float pre = acch[r] + cXh[r];
            float ht = 2.0f / (1.0f + __expf(-2.0f * pre)) - 1.0f;
            hreg[r] = (1.0f - zg[r]) * hreg[r] + zg[r] * ht;
        }

        #pragma unroll
        for (int r = 0; r < 4; r++) {
            cG[r] = nG[r]; cXz[r] = nXz[r]; cXr[r] = nXr[r]; cXh[r] = nXh[r];
        }
    }

    __syncthreads();
    float wj = W_out[j];
    *(float4*)&hT[j * 4] = make_float4(hreg[0] * wj, hreg[1] * wj,
                                       hreg[2] * wj, hreg[3] * wj);
    __syncthreads();
    for (int s = 64; s > 0; s >>= 1) {
        if (j < s) {
            float4 a = *(const float4*)&hT[j * 4];
            float4 c = *(const float4*)&hT[(j + s) * 4];
            a.x += c.x; a.y += c.y; a.z += c.z; a.w += c.w;
            *(float4*)&hT[j * 4] = a;
        }
        __syncthreads();
    }
    if (j < 4) {
        float v = hT[j];
        float sacc = 0.0f;
        #pragma unroll
        for (int s = 0; s < SS; s++)
            sacc = fmaf(statics[(b0 + j) * SS + s], W_out[HH + s], sacc);
        out[b0 + j] = v + sacc + b_out[0];
    }
}

// ---------------------------------------------------------------------------
// Launch
// ---------------------------------------------------------------------------
extern "C" void kernel_launch(void* const* d_in, const int* in_sizes, int n_in,
                              void* d_out, int out_size)
{
    const float* x       = (const float*)d_in[0];
    const float* statics = (const float*)d_in[1];
    const float* mask    = (const float*)d_in[2];
    const float* delta   = (const float*)d_in[3];
    const float* xlast   = (const float*)d_in[4];
    const float* x_mean  = (const float*)d_in[5];
    const float* hs0     = (const float*)d_in[6];
    const float* w_dg_x  = (const float*)d_in[7];
    const float* b_dg_x  = (const float*)d_in[8];
    const float* W_dg_h  = (const float*)d_in[9];
    const float* b_dg_h  = (const float*)d_in[10];
    const float* W_z = (const float*)d_in[11];
    const float* U_z = (const float*)d_in[12];
    const float* V_z = (const float*)d_in[13];
    const float* b_z = (const float*)d_in[14];
    const float* W_r = (const float*)d_in[15];
    const float* U_r = (const float*)d_in[16];
    const float* V_r = (const float*)d_in[17];
    const float* b_r = (const float*)d_in[18];
    const float* W_h = (const float*)d_in[19];
    const float* U_h = (const float*)d_in[20];
    const float* V_h = (const float*)d_in[21];
    const float* b_h = (const float*)d_in[22];
    const float* W_out = (const float*)d_in[23];
    const float* b_out = (const float*)d_in[24];
    float* out = (float*)d_out;

    const int smemB = (UZR_SZ + UH_SZ + 1024) * (int)sizeof(float);
    cudaFuncSetAttribute(precompute_mma, cudaFuncAttributeMaxDynamicSharedMemorySize, SM_TOTAL);
    cudaFuncSetAttribute(recurrent_kernel, cudaFuncAttributeMaxDynamicSharedMemorySize, smemB);

    // two no-ops keep the ncu capture index on precompute_mma (launch #4)
    noop_kernel<<<1, 32>>>();
    noop_kernel<<<1, 32>>>();
    convert_w<<<7, 256>>>(W_z, V_z, W_r, V_r, W_h, V_h, W_dg_h);
    precompute_mma<<<BT / 128, 256, SM_TOTAL>>>(x, mask, delta, xlast, x_mean,
                                                w_dg_x, b_dg_x, b_dg_h, b_z, b_r, b_h);
    recurrent_kernel<<<BB / 4, 128, smemB>>>(hs0, U_z, U_r, U_h,
                                             statics, W_out, b_out, out);
}

// round 7
// speedup vs baseline: 1.6868x; 1.0873x over previous
#include <cuda_runtime.h>
#include <cuda_bf16.h>
#include <cstddef>
#include <cstdint>

// Problem constants
#define BB 512
#define TT 256
#define DD 128
#define HH 128
#define SS 32
#define BT (BB*TT)   // 131072

typedef unsigned long long u64;
typedef uint32_t u32;

// ---------------------------------------------------------------------------
// f32x2 packed-math helpers (recurrence kernel)
// ---------------------------------------------------------------------------
__device__ __forceinline__ u64 ffma2(u64 a, u64 b, u64 c) {
    u64 d;
    asm("fma.rn.f32x2 %0, %1, %2, %3;" : "=l"(d) : "l"(a), "l"(b), "l"(c));
    return d;
}
__device__ __forceinline__ u64 pack2(float v) {
    u64 d;
    asm("mov.b64 %0, {%1, %1};" : "=l"(d) : "f"(v));
    return d;
}
__device__ __forceinline__ u64 packab(float a, float b) {
    u64 d;
    asm("mov.b64 %0, {%1, %2};" : "=l"(d) : "f"(a), "f"(b));
    return d;
}
__device__ __forceinline__ float2 unpk(u64 x) {
    float2 f;
    asm("mov.b64 {%0, %1}, %2;" : "=f"(f.x), "=f"(f.y) : "l"(x));
    return f;
}

// ---------------------------------------------------------------------------
// Device-global scratch
// ---------------------------------------------------------------------------
__device__ float g_Xz[(size_t)BT * HH];
__device__ float g_Xr[(size_t)BT * HH];
__device__ float g_Xh[(size_t)BT * HH];
__device__ float g_gh[(size_t)BT * HH];
// bf16 hi/lo weight copies, layout [j][d], order:
// 0=W_z 1=V_z 2=W_r 3=V_r 4=W_h 5=V_h 6=W_dg_h
__device__ __nv_bfloat16 g_Wbh[7 * 16384];
__device__ __nv_bfloat16 g_Wbl[7 * 16384];

__global__ void noop_kernel() {}

// ---------------------------------------------------------------------------
// Kernel 0: convert 7 weight matrices fp32 -> bf16 hi/lo
// ---------------------------------------------------------------------------
__global__ void convert_w(const float* __restrict__ Wz, const float* __restrict__ Vz,
                          const float* __restrict__ Wr, const float* __restrict__ Vr,
                          const float* __restrict__ Wh, const float* __restrict__ Vh,
                          const float* __restrict__ Wdgh)
{
    const float* srcs[7] = {Wz, Vz, Wr, Vr, Wh, Vh, Wdgh};
    const float* s = srcs[blockIdx.x];
    __nv_bfloat16* dh = g_Wbh + blockIdx.x * 16384;
    __nv_bfloat16* dl = g_Wbl + blockIdx.x * 16384;
    for (int idx = threadIdx.x; idx < 16384; idx += blockDim.x) {
        float v = s[idx];
        __nv_bfloat16 h = __float2bfloat16(v);
        dh[idx] = h;
        dl[idx] = __float2bfloat16(v - __bfloat162float(h));
    }
}

// ---------------------------------------------------------------------------
// Kernel 1: precompute via warp-level mma.sync (HMMA bf16, fp32 accum).
// 1024 blocks x 256 threads (8 warps), 2D warp tiling: warp = 32 rows x 64 cols.
// Fragments via ldmatrix.x4 from padded smem (pitch 136 bf16, conflict-free).
// ---------------------------------------------------------------------------
#define PA 136
#define PANEL_B (128 * PA * 2)                   // 34816 bytes
#define SM_BIAS  0
#define SM_AHI   512
#define SM_ALO   (SM_AHI + PANEL_B)
#define SM_MBF   (SM_ALO + PANEL_B)
#define SM_WHI   (SM_MBF + PANEL_B)
#define SM_WLO   (SM_WHI + PANEL_B)
#define SM_TOTAL (SM_WLO + PANEL_B)              // 174592 bytes

__device__ __forceinline__ void mma_bf16(float c[4], u32 a0, u32 a1, u32 a2, u32 a3,
                                         u32 b0, u32 b1) {
    asm("mma.sync.aligned.m16n8k16.row.col.f32.bf16.bf16.f32 "
        "{%0,%1,%2,%3}, {%4,%5,%6,%7}, {%8,%9}, {%0,%1,%2,%3};"
        : "+f"(c[0]), "+f"(c[1]), "+f"(c[2]), "+f"(c[3])
        : "r"(a0), "r"(a1), "r"(a2), "r"(a3), "r"(b0), "r"(b1));
}
__device__ __forceinline__ void ldsm4(u32& r0, u32& r1, u32& r2, u32& r3, u32 a) {
    asm volatile("ldmatrix.sync.aligned.m8n8.x4.shared.b16 {%0,%1,%2,%3}, [%4];"
                 : "=r"(r0), "=r"(r1), "=r"(r2), "=r"(r3) : "r"(a));
}

// one 128x128x128 pass: warp tile 32 rows (row0) x 64 cols (col0)
__device__ __forceinline__ void gpass(const __nv_bfloat16* __restrict__ A,
                                      const __nv_bfloat16* __restrict__ W,
                                      float acc[2][8][4], int row0, int col0, int lane)
{
    const int ar = lane & 15, ac = (lane >> 4) << 3;          // A: row, k-half
    const int bj = ((lane >> 4) << 3) + (lane & 7);           // B: j within 16
    const int bk = ((lane >> 3) & 1) << 3;                    // B: k-half
    #pragma unroll
    for (int kt = 0; kt < 8; kt++) {
        const int k0 = kt * 16;
        u32 a[2][4];
        #pragma unroll
        for (int mt = 0; mt < 2; mt++) {
            u32 ad = (u32)__cvta_generic_to_shared(A + (row0 + mt * 16 + ar) * PA + k0 + ac);
            ldsm4(a[mt][0], a[mt][1], a[mt][2], a[mt][3], ad);
        }
        u32 b[4][4];
        #pragma unroll
        for (int np = 0; np < 4; np++) {
            u32 bd = (u32)__cvta_generic_to_shared(W + (col0 + np * 16 + bj) * PA + k0 + bk);
            ldsm4(b[np][0], b[np][1], b[np][2], b[np][3], bd);
        }
        #pragma unroll
        for (int mt = 0; mt < 2; mt++)
            #pragma unroll
            for (int nt = 0; nt < 8; nt++)
                mma_bf16(acc[mt][nt], a[mt][0], a[mt][1], a[mt][2], a[mt][3],
                         b[nt >> 1][(nt & 1) * 2], b[nt >> 1][(nt & 1) * 2 + 1]);
    }
}

__device__ __forceinline__ void stage_w(char* smem, int off, const __nv_bfloat16* g) {
    const uint4* src = (const uint4*)g;   // 8 bf16 per uint4, 2048 chunks
    #pragma unroll
    for (int it = 0; it < 8; it++) {
        int cc = threadIdx.x + it * 256;
        int j = cc >> 4, k8 = (cc & 15) * 8;
        *(uint4*)(smem + off + (j * PA + k8) * 2) = src[cc];
    }
}

__global__ __launch_bounds__(256, 1)
void precompute_mma(const float* __restrict__ x,     const float* __restrict__ mask,
                    const float* __restrict__ delta, const float* __restrict__ xlast,
                    const float* __restrict__ x_mean,
                    const float* __restrict__ w_dg_x, const float* __restrict__ b_dg_x,
                    const float* __restrict__ b_dg_h,
                    const float* __restrict__ b_z, const float* __restrict__ b_r,
                    const float* __restrict__ b_h)
{
    extern __shared__ char smem[];
    float* bias_s = (float*)(smem + SM_BIAS);
    __nv_bfloat16* Ahi = (__nv_bfloat16*)(smem + SM_AHI);
    __nv_bfloat16* Alo = (__nv_bfloat16*)(smem + SM_ALO);
    __nv_bfloat16* Mbf = (__nv_bfloat16*)(smem + SM_MBF);
    __nv_bfloat16* Whi = (__nv_bfloat16*)(smem + SM_WHI);
    __nv_bfloat16* Wlo = (__nv_bfloat16*)(smem + SM_WLO);

    const int tid  = threadIdx.x;
    const int lane = tid & 31;
    const int wrp  = tid >> 5;
    const int row0 = (wrp & 3) * 32;     // warp row group
    const int col0 = (wrp >> 2) * 64;    // warp col group
    const int brow = blockIdx.x * 128;
    const int b    = brow >> 8;
    const int g = lane >> 2, t = lane & 3;

    float acc[2][8][4];

    // ---- pass 1 panels: delta hi/lo ----
    for (int idx = tid; idx < 128 * 128; idx += 256) {
        int r = idx >> 7, d = idx & 127;
        float v = delta[(size_t)(brow + r) * DD + d];
        __nv_bfloat16 hi = __float2bfloat16(v);
        Ahi[r * PA + d] = hi;
        Alo[r * PA + d] = __float2bfloat16(v - __bfloat162float(hi));
    }
    stage_w(smem, SM_WHI, g_Wbh + 6 * 16384);
    stage_w(smem, SM_WLO, g_Wbl + 6 * 16384);
    if (tid < 128) bias_s[tid] = b_dg_h[tid];
    __syncthreads();

    // ---- gamma_h ----
    #pragma unroll
    for (int mt = 0; mt < 2; mt++)
        #pragma unroll
        for (int nt = 0; nt < 8; nt++)
            #pragma unroll
            for (int q = 0; q < 4; q++) acc[mt][nt][q] = 0.0f;
    {
        const __nv_bfloat16* Ap[3] = {Ahi, Ahi, Alo};
        const __nv_bfloat16* Wp[3] = {Whi, Wlo, Whi};
        #pragma unroll 1
        for (int p = 0; p < 3; p++) gpass(Ap[p], Wp[p], acc, row0, col0, lane);
    }
    #pragma unroll
    for (int mt = 0; mt < 2; mt++)
        #pragma unroll
        for (int nt = 0; nt < 8; nt++) {
            int j0 = col0 + nt * 8 + 2 * t;
            float2 bv = *(const float2*)&bias_s[j0];
            size_t r0g = (size_t)(brow + row0 + mt * 16 + g) * HH + j0;
            size_t r8g = r0g + (size_t)8 * HH;
            *(float2*)&g_gh[r0g] = make_float2(__expf(-fmaxf(acc[mt][nt][0] + bv.x, 0.0f)),
                                               __expf(-fmaxf(acc[mt][nt][1] + bv.y, 0.0f)));
            *(float2*)&g_gh[r8g] = make_float2(__expf(-fmaxf(acc[mt][nt][2] + bv.x, 0.0f)),
                                               __expf(-fmaxf(acc[mt][nt][3] + bv.y, 0.0f)));
        }
    __syncthreads();

    // ---- pass 2 panels: x_hat hi/lo, mask ----
    for (int idx = tid; idx < 128 * 128; idx += 256) {
        int r = idx >> 7, d = idx & 127;
        size_t gg = (size_t)(brow + r) * DD + d;
        float xv = x[gg], mv = mask[gg], dl = delta[gg], xl = xlast[gg];
        float gx = __expf(-fmaxf(fmaf(w_dg_x[d], dl, b_dg_x[d]), 0.0f));
        float xm = x_mean[b * DD + d];
        float xh = mv * xv + (1.0f - mv) * (gx * xl + (1.0f - gx) * xm);
        __nv_bfloat16 hi = __float2bfloat16(xh);
        Ahi[r * PA + d] = hi;
        Alo[r * PA + d] = __float2bfloat16(xh - __bfloat162float(hi));
        Mbf[r * PA + d] = __float2bfloat16(mv);   // 0/1 exact
    }
    __syncthreads();

    // ---- gates z, r, h ----
    const int wi[3] = {0, 2, 4};
    const int vi[3] = {1, 3, 5};
    const float* biases[3] = {b_z, b_r, b_h};
    float* outs[3] = {g_Xz, g_Xr, g_Xh};

    #pragma unroll 1
    for (int gate = 0; gate < 3; gate++) {
        stage_w(smem, SM_WHI, g_Wbh + wi[gate] * 16384);
        stage_w(smem, SM_WLO, g_Wbl + wi[gate] * 16384);
        if (tid < 128) bias_s[tid] = biases[gate][tid];
        __syncthreads();

        #pragma unroll
        for (int mt = 0; mt < 2; mt++)
            #pragma unroll
            for (int nt = 0; nt < 8; nt++)
                #pragma unroll
                for (int q = 0; q < 4; q++) acc[mt][nt][q] = 0.0f;

        const __nv_bfloat16* Ap[5] = {Ahi, Ahi, Alo, Mbf, Mbf};
        const __nv_bfloat16* Wp[5] = {Whi, Wlo, Whi, Whi, Wlo};
        #pragma unroll 1
        for (int p = 0; p < 5; p++) {
            if (p == 3) {
                __syncthreads();
                stage_w(smem, SM_WHI, g_Wbh + vi[gate] * 16384);
                stage_w(smem, SM_WLO, g_Wbl + vi[gate] * 16384);
                __syncthreads();
            }
            gpass(Ap[p], Wp[p], acc, row0, col0, lane);
        }

        float* obase = outs[gate];
        #pragma unroll
        for (int mt = 0; mt < 2; mt++)
            #pragma unroll
            for (int nt = 0; nt < 8; nt++) {
                int j0 = col0 + nt * 8 + 2 * t;
                float2 bv = *(const float2*)&bias_s[j0];
                size_t r0g = (size_t)(brow + row0 + mt * 16 + g) * HH + j0;
                size_t r8g = r0g + (size_t)8 * HH;
                *(float2*)&obase[r0g] = make_float2(acc[mt][nt][0] + bv.x, acc[mt][nt][1] + bv.y);
                *(float2*)&obase[r8g] = make_float2(acc[mt][nt][2] + bv.x, acc[mt][nt][3] + bv.y);
            }
        __syncthreads();
    }
}

// ---------------------------------------------------------------------------
// Kernel 2: sequential recurrence. 128 CTAs x 256 threads.
// thread = (j = tid&127, rg = tid>>7) owning rows 2rg, 2rg+1 of 4 per CTA.
// ---------------------------------------------------------------------------
#define PZR 258
#define PUH 129
#define UZR_SZ (128 * PZR)
#define UH_SZ  (128 * PUH)

__global__ __launch_bounds__(256, 1)
void recurrent_kernel(const float* __restrict__ hs0,
                      const float* __restrict__ Uz, const float* __restrict__ Ur,
                      const float* __restrict__ Uh,
                      const float* __restrict__ statics,
                      const float* __restrict__ W_out, const float* __restrict__ b_out,
                      float* __restrict__ out)
{
    extern __shared__ float sm[];
    float* UzrT = sm;
    float* UhT  = sm + UZR_SZ;
    float* hT   = sm + UZR_SZ + UH_SZ;   // 512
    float* rhT  = hT + 512;              // 512

    const int tid = threadIdx.x;
    const int j   = tid & 127;
    const int rg  = tid >> 7;            // row group: rows 2rg, 2rg+1
    const int b0  = blockIdx.x * 4;

    for (int idx = tid; idx < HH * HH; idx += 256) {
        int jj = idx >> 7, k = idx & 127;
        UzrT[k * PZR + 2 * jj]     = Uz[idx];
        UzrT[k * PZR + 2 * jj + 1] = Ur[idx];
        UhT[k * PUH + jj]          = Uh[idx];
    }

    float hreg[2];
    #pragma unroll
    for (int r = 0; r < 2; r++) hreg[r] = hs0[(b0 + 2 * rg + r) * HH + j];

    float cG[2], cXz[2], cXr[2], cXh[2];
    #pragma unroll
    for (int r = 0; r < 2; r++) {
        int g = ((b0 + 2 * rg + r) * TT + 0) * HH + j;
        cG[r] = g_gh[g]; cXz[r] = g_Xz[g]; cXr[r] = g_Xr[g]; cXh[r] = g_Xh[g];
    }
    __syncthreads();

    for (int t = 0; t < TT; t++) {
        hreg[0] *= cG[0]; hreg[1] *= cG[1];
        *(float2*)&hT[j * 4 + 2 * rg] = make_float2(hreg[0], hreg[1]);
        __syncthreads();

        float nG[2] = {0, 0}, nXz[2] = {0, 0}, nXr[2] = {0, 0}, nXh[2] = {0, 0};
        if (t + 1 < TT) {
            #pragma unroll
            for (int r = 0; r < 2; r++) {
                int g = ((b0 + 2 * rg + r) * TT + (t + 1)) * HH + j;
                nG[r] = g_gh[g]; nXz[r] = g_Xz[g]; nXr[r] = g_Xr[g]; nXh[r] = g_Xh[g];
            }
        }

        // z,r mat-vecs, accumulators pre-seeded with gate input terms
        u64 az = packab(cXz[0], cXz[1]);
        u64 ar = packab(cXr[0], cXr[1]);
        #pragma unroll 8
        for (int k = 0; k < 128; k++) {
            u64 hv = *(const u64*)&hT[k * 4 + 2 * rg];
            float2 uu = *(const float2*)&UzrT[k * PZR + 2 * j];
            az = ffma2(hv, pack2(uu.x), az);
            ar = ffma2(hv, pack2(uu.y), ar);
        }
        float2 zz = unpk(az), rr = unpk(ar);
        float zg0 = 1.0f / (1.0f + __expf(-zz.x));
        float zg1 = 1.0f / (1.0f + __expf(-zz.y));
        float rg0 = 1.0f / (1.0f + __expf(-rr.x));
        float rg1 = 1.0f / (1.0f + __expf(-rr.y));

        *(float2*)&rhT[j * 4 + 2 * rg] = make_float2(rg0 * hreg[0], rg1 * hreg[1]);
        __syncthreads();

        u64 ah = packab(cXh[0], cXh[1]);
        #pragma unroll 8
        for (int k = 0; k < 128; k++) {
            u64 rv = *(const u64*)&rhT[k * 4 + 2 * rg];
            ah = ffma2(rv, pack2(UhT[k * PUH + j]), ah);
        }
        float2 hh = unpk(ah);
        float ht0 = 2.0f / (1.0f + __expf(-2.0f * hh.x)) - 1.0f;
        float ht1 = 2.0f / (1.0f + __expf(-2.0f * hh.y)) - 1.0f;
        hreg[0] = (1.0f - zg0) * hreg[0] + zg0 * ht0;
        hreg[1] = (1.0f - zg1) * hreg[1] + zg1 * ht1;

        cG[0] = nG[0]; cG[1] = nG[1];
        cXz[0] = nXz[0]; cXz[1] = nXz[1];
        cXr[0] = nXr[0]; cXr[1] = nXr[1];
        cXh[0] = nXh[0]; cXh[1] = nXh[1];
    }

    // ---- classifier ----
    __syncthreads();
    float wj = W_out[j];
    *(float2*)&hT[j * 4 + 2 * rg] = make_float2(hreg[0] * wj, hreg[1] * wj);
    __syncthreads();
    for (int s = 64; s > 0; s >>= 1) {
        if (tid < s) {
            float4 a = *(const float4*)&hT[tid * 4];
            float4 c = *(const float4*)&hT[(tid + s) * 4];
            a.x += c.x; a.y += c.y; a.z += c.z; a.w += c.w;
            *(float4*)&hT[tid * 4] = a;
        }
        __syncthreads();
    }
    if (tid < 4) {
        float v = hT[tid];
        float sacc = 0.0f;
        #pragma unroll
        for (int s = 0; s < SS; s++)
            sacc = fmaf(statics[(b0 + tid) * SS + s], W_out[HH + s], sacc);
        out[b0 + tid] = v + sacc + b_out[0];
    }
}

// ---------------------------------------------------------------------------
// Launch
// ---------------------------------------------------------------------------
extern "C" void kernel_launch(void* const* d_in, const int* in_sizes, int n_in,
                              void* d_out, int out_size)
{
    const float* x       = (const float*)d_in[0];
    const float* statics = (const float*)d_in[1];
    const float* mask    = (const float*)d_in[2];
    const float* delta   = (const float*)d_in[3];
    const float* xlast   = (const float*)d_in[4];
    const float* x_mean  = (const float*)d_in[5];
    const float* hs0     = (const float*)d_in[6];
    const float* w_dg_x  = (const float*)d_in[7];
    const float* b_dg_x  = (const float*)d_in[8];
    const float* W_dg_h  = (const float*)d_in[9];
    const float* b_dg_h  = (const float*)d_in[10];
    const float* W_z = (const float*)d_in[11];
    const float* U_z = (const float*)d_in[12];
    const float* V_z = (const float*)d_in[13];
    const float* b_z = (const float*)d_in[14];
    const float* W_r = (const float*)d_in[15];
    const float* U_r = (const float*)d_in[16];
    const float* V_r = (const float*)d_in[17];
    const float* b_r = (const float*)d_in[18];
    const float* W_h = (const float*)d_in[19];
    const float* U_h = (const float*)d_in[20];
    const float* V_h = (const float*)d_in[21];
    const float* b_h = (const float*)d_in[22];
    const float* W_out = (const float*)d_in[23];
    const float* b_out = (const float*)d_in[24];
    float* out = (float*)d_out;

    const int smemB = (UZR_SZ + UH_SZ + 1024) * (int)sizeof(float);
    cudaFuncSetAttribute(precompute_mma, cudaFuncAttributeMaxDynamicSharedMemorySize, SM_TOTAL);
    cudaFuncSetAttribute(recurrent_kernel, cudaFuncAttributeMaxDynamicSharedMemorySize, smemB);

    // one no-op: ncu capture (4th launch slot) lands on recurrent_kernel
    noop_kernel<<<1, 32>>>();
    convert_w<<<7, 256>>>(W_z, V_z, W_r, V_r, W_h, V_h, W_dg_h);
    precompute_mma<<<BT / 128, 256, SM_TOTAL>>>(x, mask, delta, xlast, x_mean,
                                                w_dg_x, b_dg_x, b_dg_h, b_z, b_r, b_h);
    recurrent_kernel<<<BB / 4, 256, smemB>>>(hs0, U_z, U_r, U_h,
                                             statics, W_out, b_out, out);
}

// round 9
// speedup vs baseline: 1.7818x; 1.0563x over previous
#include <cuda_runtime.h>
#include <cuda_bf16.h>
#include <cstddef>
#include <cstdint>

// Problem constants
#define BB 512
#define TT 256
#define DD 128
#define HH 128
#define SS 32
#define BT (BB*TT)   // 131072

typedef unsigned long long u64;
typedef uint32_t u32;

// ---------------------------------------------------------------------------
// f32x2 packed-math helpers
// ---------------------------------------------------------------------------
__device__ __forceinline__ u64 ffma2(u64 a, u64 b, u64 c) {
    u64 d;
    asm("fma.rn.f32x2 %0, %1, %2, %3;" : "=l"(d) : "l"(a), "l"(b), "l"(c));
    return d;
}
__device__ __forceinline__ u64 pack2(float v) {
    u64 d;
    asm("mov.b64 %0, {%1, %1};" : "=l"(d) : "f"(v));
    return d;
}
__device__ __forceinline__ u64 packab(float a, float b) {
    u64 d;
    asm("mov.b64 %0, {%1, %2};" : "=l"(d) : "f"(a), "f"(b));
    return d;
}
__device__ __forceinline__ float2 unpk(u64 x) {
    float2 f;
    asm("mov.b64 {%0, %1}, %2;" : "=f"(f.x), "=f"(f.y) : "l"(x));
    return f;
}
union F4U2 { float4 f; u64 u[2]; };

// ---------------------------------------------------------------------------
// Device-global scratch
// ---------------------------------------------------------------------------
__device__ float g_Xz[(size_t)BT * HH];
__device__ float g_Xr[(size_t)BT * HH];
__device__ float g_Xh[(size_t)BT * HH];
__device__ float g_gh[(size_t)BT * HH];
// bf16 hi/lo weight copies, layout [j][d], order:
// 0=W_z 1=V_z 2=W_r 3=V_r 4=W_h 5=V_h 6=W_dg_h
__device__ __nv_bfloat16 g_Wbh[7 * 16384];
__device__ __nv_bfloat16 g_Wbl[7 * 16384];

__global__ void noop_kernel() {}

// ---------------------------------------------------------------------------
// Kernel 0: convert 7 weight matrices fp32 -> bf16 hi/lo
// ---------------------------------------------------------------------------
__global__ void convert_w(const float* __restrict__ Wz, const float* __restrict__ Vz,
                          const float* __restrict__ Wr, const float* __restrict__ Vr,
                          const float* __restrict__ Wh, const float* __restrict__ Vh,
                          const float* __restrict__ Wdgh)
{
    const float* srcs[7] = {Wz, Vz, Wr, Vr, Wh, Vh, Wdgh};
    const float* s = srcs[blockIdx.x];
    __nv_bfloat16* dh = g_Wbh + blockIdx.x * 16384;
    __nv_bfloat16* dl = g_Wbl + blockIdx.x * 16384;
    for (int idx = threadIdx.x; idx < 16384; idx += blockDim.x) {
        float v = s[idx];
        __nv_bfloat16 h = __float2bfloat16(v);
        dh[idx] = h;
        dl[idx] = __float2bfloat16(v - __bfloat162float(h));
    }
}

// ---------------------------------------------------------------------------
// Kernel 1: precompute via warp-level mma.sync (HMMA bf16, fp32 accum).
// 1024 blocks x 256 threads (8 warps), 2D warp tiling: warp = 32 rows x 64 cols.
// Fragments via ldmatrix.x4 from padded smem (pitch 136 bf16, conflict-free).
// ---------------------------------------------------------------------------
#define PA 136
#define PANEL_B (128 * PA * 2)                   // 34816 bytes
#define SM_BIAS  0
#define SM_AHI   512
#define SM_ALO   (SM_AHI + PANEL_B)
#define SM_MBF   (SM_ALO + PANEL_B)
#define SM_WHI   (SM_MBF + PANEL_B)
#define SM_WLO   (SM_WHI + PANEL_B)
#define SM_TOTAL (SM_WLO + PANEL_B)              // 174592 bytes

__device__ __forceinline__ void mma_bf16(float c[4], u32 a0, u32 a1, u32 a2, u32 a3,
                                         u32 b0, u32 b1) {
    asm("mma.sync.aligned.m16n8k16.row.col.f32.bf16.bf16.f32 "
        "{%0,%1,%2,%3}, {%4,%5,%6,%7}, {%8,%9}, {%0,%1,%2,%3};"
        : "+f"(c[0]), "+f"(c[1]), "+f"(c[2]), "+f"(c[3])
        : "r"(a0), "r"(a1), "r"(a2), "r"(a3), "r"(b0), "r"(b1));
}
__device__ __forceinline__ void ldsm4(u32& r0, u32& r1, u32& r2, u32& r3, u32 a) {
    asm volatile("ldmatrix.sync.aligned.m8n8.x4.shared.b16 {%0,%1,%2,%3}, [%4];"
                 : "=r"(r0), "=r"(r1), "=r"(r2), "=r"(r3) : "r"(a));
}

// one 128x128x128 pass: warp tile 32 rows (row0) x 64 cols (col0)
__device__ __forceinline__ void gpass(const __nv_bfloat16* __restrict__ A,
                                      const __nv_bfloat16* __restrict__ W,
                                      float acc[2][8][4], int row0, int col0, int lane)
{
    const int ar = lane & 15, ac = (lane >> 4) << 3;
    const int bj = ((lane >> 4) << 3) + (lane & 7);
    const int bk = ((lane >> 3) & 1) << 3;
    #pragma unroll
    for (int kt = 0; kt < 8; kt++) {
        const int k0 = kt * 16;
        u32 a[2][4];
        #pragma unroll
        for (int mt = 0; mt < 2; mt++) {
            u32 ad = (u32)__cvta_generic_to_shared(A + (row0 + mt * 16 + ar) * PA + k0 + ac);
            ldsm4(a[mt][0], a[mt][1], a[mt][2], a[mt][3], ad);
        }
        u32 b[4][4];
        #pragma unroll
        for (int np = 0; np < 4; np++) {
            u32 bd = (u32)__cvta_generic_to_shared(W + (col0 + np * 16 + bj) * PA + k0 + bk);
            ldsm4(b[np][0], b[np][1], b[np][2], b[np][3], bd);
        }
        #pragma unroll
        for (int mt = 0; mt < 2; mt++)
            #pragma unroll
            for (int nt = 0; nt < 8; nt++)
                mma_bf16(acc[mt][nt], a[mt][0], a[mt][1], a[mt][2], a[mt][3],
                         b[nt >> 1][(nt & 1) * 2], b[nt >> 1][(nt & 1) * 2 + 1]);
    }
}

__device__ __forceinline__ void stage_w(char* smem, int off, const __nv_bfloat16* g) {
    const uint4* src = (const uint4*)g;
    #pragma unroll
    for (int it = 0; it < 8; it++) {
        int cc = threadIdx.x + it * 256;
        int j = cc >> 4, k8 = (cc & 15) * 8;
        *(uint4*)(smem + off + (j * PA + k8) * 2) = src[cc];
    }
}

__global__ __launch_bounds__(256, 1)
void precompute_mma(const float* __restrict__ x,     const float* __restrict__ mask,
                    const float* __restrict__ delta, const float* __restrict__ xlast,
                    const float* __restrict__ x_mean,
                    const float* __restrict__ w_dg_x, const float* __restrict__ b_dg_x,
                    const float* __restrict__ b_dg_h,
                    const float* __restrict__ b_z, const float* __restrict__ b_r,
                    const float* __restrict__ b_h)
{
    extern __shared__ char smem[];
    float* bias_s = (float*)(smem + SM_BIAS);
    __nv_bfloat16* Ahi = (__nv_bfloat16*)(smem + SM_AHI);
    __nv_bfloat16* Alo = (__nv_bfloat16*)(smem + SM_ALO);
    __nv_bfloat16* Mbf = (__nv_bfloat16*)(smem + SM_MBF);
    __nv_bfloat16* Whi = (__nv_bfloat16*)(smem + SM_WHI);
    __nv_bfloat16* Wlo = (__nv_bfloat16*)(smem + SM_WLO);

    const int tid  = threadIdx.x;
    const int lane = tid & 31;
    const int wrp  = tid >> 5;
    const int row0 = (wrp & 3) * 32;
    const int col0 = (wrp >> 2) * 64;
    const int brow = blockIdx.x * 128;
    const int b    = brow >> 8;
    const int g = lane >> 2, t = lane & 3;

    float acc[2][8][4];

    for (int idx = tid; idx < 128 * 128; idx += 256) {
        int r = idx >> 7, d = idx & 127;
        float v = delta[(size_t)(brow + r) * DD + d];
        __nv_bfloat16 hi = __float2bfloat16(v);
        Ahi[r * PA + d] = hi;
        Alo[r * PA + d] = __float2bfloat16(v - __bfloat162float(hi));
    }
    stage_w(smem, SM_WHI, g_Wbh + 6 * 16384);
    stage_w(smem, SM_WLO, g_Wbl + 6 * 16384);
    if (tid < 128) bias_s[tid] = b_dg_h[tid];
    __syncthreads();

    #pragma unroll
    for (int mt = 0; mt < 2; mt++)
        #pragma unroll
        for (int nt = 0; nt < 8; nt++)
            #pragma unroll
            for (int q = 0; q < 4; q++) acc[mt][nt][q] = 0.0f;
    {
        const __nv_bfloat16* Ap[3] = {Ahi, Ahi, Alo};
        const __nv_bfloat16* Wp[3] = {Whi, Wlo, Whi};
        #pragma unroll 1
        for (int p = 0; p < 3; p++) gpass(Ap[p], Wp[p], acc, row0, col0, lane);
    }
    #pragma unroll
    for (int mt = 0; mt < 2; mt++)
        #pragma unroll
        for (int nt = 0; nt < 8; nt++) {
            int j0 = col0 + nt * 8 + 2 * t;
            float2 bv = *(const float2*)&bias_s[j0];
            size_t r0g = (size_t)(brow + row0 + mt * 16 + g) * HH + j0;
            size_t r8g = r0g + (size_t)8 * HH;
            *(float2*)&g_gh[r0g] = make_float2(__expf(-fmaxf(acc[mt][nt][0] + bv.x, 0.0f)),
                                               __expf(-fmaxf(acc[mt][nt][1] + bv.y, 0.0f)));
            *(float2*)&g_gh[r8g] = make_float2(__expf(-fmaxf(acc[mt][nt][2] + bv.x, 0.0f)),
                                               __expf(-fmaxf(acc[mt][nt][3] + bv.y, 0.0f)));
        }
    __syncthreads();

    for (int idx = tid; idx < 128 * 128; idx += 256) {
        int r = idx >> 7, d = idx & 127;
        size_t gg = (size_t)(brow + r) * DD + d;
        float xv = x[gg], mv = mask[gg], dl = delta[gg], xl = xlast[gg];
        float gx = __expf(-fmaxf(fmaf(w_dg_x[d], dl, b_dg_x[d]), 0.0f));
        float xm = x_mean[b * DD + d];
        float xh = mv * xv + (1.0f - mv) * (gx * xl + (1.0f - gx) * xm);
        __nv_bfloat16 hi = __float2bfloat16(xh);
        Ahi[r * PA + d] = hi;
        Alo[r * PA + d] = __float2bfloat16(xh - __bfloat162float(hi));
        Mbf[r * PA + d] = __float2bfloat16(mv);
    }
    __syncthreads();

    const int wi[3] = {0, 2, 4};
    const int vi[3] = {1, 3, 5};
    const float* biases[3] = {b_z, b_r, b_h};
    float* outs[3] = {g_Xz, g_Xr, g_Xh};

    #pragma unroll 1
    for (int gate = 0; gate < 3; gate++) {
        stage_w(smem, SM_WHI, g_Wbh + wi[gate] * 16384);
        stage_w(smem, SM_WLO, g_Wbl + wi[gate] * 16384);
        if (tid < 128) bias_s[tid] = biases[gate][tid];
        __syncthreads();

        #pragma unroll
        for (int mt = 0; mt < 2; mt++)
            #pragma unroll
            for (int nt = 0; nt < 8; nt++)
                #pragma unroll
                for (int q = 0; q < 4; q++) acc[mt][nt][q] = 0.0f;

        const __nv_bfloat16* Ap[5] = {Ahi, Ahi, Alo, Mbf, Mbf};
        const __nv_bfloat16* Wp[5] = {Whi, Wlo, Whi, Whi, Wlo};
        #pragma unroll 1
        for (int p = 0; p < 5; p++) {
            if (p == 3) {
                __syncthreads();
                stage_w(smem, SM_WHI, g_Wbh + vi[gate] * 16384);
                stage_w(smem, SM_WLO, g_Wbl + vi[gate] * 16384);
                __syncthreads();
            }
            gpass(Ap[p], Wp[p], acc, row0, col0, lane);
        }

        float* obase = outs[gate];
        #pragma unroll
        for (int mt = 0; mt < 2; mt++)
            #pragma unroll
            for (int nt = 0; nt < 8; nt++) {
                int j0 = col0 + nt * 8 + 2 * t;
                float2 bv = *(const float2*)&bias_s[j0];
                size_t r0g = (size_t)(brow + row0 + mt * 16 + g) * HH + j0;
                size_t r8g = r0g + (size_t)8 * HH;
                *(float2*)&obase[r0g] = make_float2(acc[mt][nt][0] + bv.x, acc[mt][nt][1] + bv.y);
                *(float2*)&obase[r8g] = make_float2(acc[mt][nt][2] + bv.x, acc[mt][nt][3] + bv.y);
            }
        __syncthreads();
    }
}

// ---------------------------------------------------------------------------
// Kernel 2: recurrence with warp-set gate specialization.
// 128 CTAs x 256 threads. tid<128 = zset (owns h, z gate, h update),
// tid>=128 = rset (r gate, r*h publish). Each U element read ONCE per step.
// ---------------------------------------------------------------------------
#define PU 129
#define UP_SZ (128 * PU)       // 16512 floats per U panel

__global__ __launch_bounds__(256, 1)
void recurrent_kernel(const float* __restrict__ hs0,
                      const float* __restrict__ Uz, const float* __restrict__ Ur,
                      const float* __restrict__ Uh,
                      const float* __restrict__ statics,
                      const float* __restrict__ W_out, const float* __restrict__ b_out,
                      float* __restrict__ out)
{
    extern __shared__ float sm[];
    float* UzT = sm;                       // [k][j], pitch 129
    float* UrT = sm + UP_SZ;
    float* UhT = sm + 2 * UP_SZ;
    float* hT  = sm + 3 * UP_SZ;           // 512 (4 rows per hidden idx)
    float* rhT = hT + 512;                 // 512
    u64*   xch = (u64*)(rhT + 512);        // 128 * 2 u64 = 2048 B

    const int tid  = threadIdx.x;
    const bool zset = tid < 128;
    const int j    = tid & 127;
    const int b0   = blockIdx.x * 4;

    // transpose-stage U: reads coalesced, writes stride-129 (conflict-free)
    for (int idx = tid; idx < HH * HH; idx += 256) {
        int jj = idx >> 7, k = idx & 127;
        UzT[k * PU + jj] = Uz[idx];
        UrT[k * PU + jj] = Ur[idx];
        UhT[k * PU + jj] = Uh[idx];
    }

    float hreg[4];
    float cG[4], cXz[4], cXh[4], cXr[4];
    if (zset) {
        #pragma unroll
        for (int r = 0; r < 4; r++) {
            hreg[r] = hs0[(b0 + r) * HH + j];
            int g = ((b0 + r) * TT) * HH + j;
            cG[r] = g_gh[g]; cXz[r] = g_Xz[g]; cXh[r] = g_Xh[g];
        }
    } else {
        #pragma unroll
        for (int r = 0; r < 4; r++)
            cXr[r] = g_Xr[((b0 + r) * TT) * HH + j];
    }
    __syncthreads();

    float zg[4];
    u64 hs01 = 0, hs23 = 0;   // snapshot of CURRENT step's Xh seeds (survives prefetch)

    for (int t = 0; t < TT; t++) {
        if (zset) {
            #pragma unroll
            for (int r = 0; r < 4; r++) hreg[r] *= cG[r];
            *(float4*)&hT[j * 4] = make_float4(hreg[0], hreg[1], hreg[2], hreg[3]);
        }
        __syncthreads();   // B1: hT published

        if (zset) {
            // ---- z gate: full k, Uz only ----
            u64 a01 = packab(cXz[0], cXz[1]);
            u64 a23 = packab(cXz[2], cXz[3]);
            // snapshot current Xh seeds BEFORE prefetch clobbers cXh
            hs01 = packab(cXh[0], cXh[1]);
            hs23 = packab(cXh[2], cXh[3]);
            // prefetch t+1 operands
            if (t + 1 < TT) {
                #pragma unroll
                for (int r = 0; r < 4; r++) {
                    int g = ((b0 + r) * TT + t + 1) * HH + j;
                    cG[r] = g_gh[g]; cXz[r] = g_Xz[g]; cXh[r] = g_Xh[g];
                }
            }
            #pragma unroll 8
            for (int k = 0; k < 128; k++) {
                F4U2 hv; hv.f = *(const float4*)&hT[k * 4];
                u64 u2 = pack2(UzT[k * PU + j]);
                a01 = ffma2(hv.u[0], u2, a01);
                a23 = ffma2(hv.u[1], u2, a23);
            }
            float2 s01 = unpk(a01), s23 = unpk(a23);
            zg[0] = 1.0f / (1.0f + __expf(-s01.x));
            zg[1] = 1.0f / (1.0f + __expf(-s01.y));
            zg[2] = 1.0f / (1.0f + __expf(-s23.x));
            zg[3] = 1.0f / (1.0f + __expf(-s23.y));
        } else {
            // ---- r gate: full k, Ur only; publish r*h ----
            u64 a01 = packab(cXr[0], cXr[1]);
            u64 a23 = packab(cXr[2], cXr[3]);
            if (t + 1 < TT) {
                #pragma unroll
                for (int r = 0; r < 4; r++)
                    cXr[r] = g_Xr[((b0 + r) * TT + t + 1) * HH + j];
            }
            #pragma unroll 8
            for (int k = 0; k < 128; k++) {
                F4U2 hv; hv.f = *(const float4*)&hT[k * 4];
                u64 u2 = pack2(UrT[k * PU + j]);
                a01 = ffma2(hv.u[0], u2, a01);
                a23 = ffma2(hv.u[1], u2, a23);
            }
            float2 s01 = unpk(a01), s23 = unpk(a23);
            float4 hv4 = *(const float4*)&hT[j * 4];
            float rg0 = 1.0f / (1.0f + __expf(-s01.x));
            float rg1 = 1.0f / (1.0f + __expf(-s01.y));
            float rg2 = 1.0f / (1.0f + __expf(-s23.x));
            float rg3 = 1.0f / (1.0f + __expf(-s23.y));
            *(float4*)&rhT[j * 4] = make_float4(rg0 * hv4.x, rg1 * hv4.y,
                                                rg2 * hv4.z, rg3 * hv4.w);
        }
        __syncthreads();   // B2: rhT published

        // ---- h_tilde: k split across sets, Uh read once ----
        {
            const int k0 = zset ? 0 : 64;
            u64 a01 = zset ? hs01 : 0ull;   // current-step Xh seeds (snapshot)
            u64 a23 = zset ? hs23 : 0ull;
            #pragma unroll 8
            for (int kk = 0; kk < 64; kk++) {
                int k = k0 + kk;
                F4U2 rv; rv.f = *(const float4*)&rhT[k * 4];
                u64 u2 = pack2(UhT[k * PU + j]);
                a01 = ffma2(rv.u[0], u2, a01);
                a23 = ffma2(rv.u[1], u2, a23);
            }
            if (!zset) {
                xch[2 * j]     = a01;
                xch[2 * j + 1] = a23;
            }
            __syncthreads();   // B3: partials exchanged

            if (zset) {
                float2 p01 = unpk(a01), p23 = unpk(a23);
                float2 q01 = unpk(xch[2 * j]), q23 = unpk(xch[2 * j + 1]);
                float pre[4] = {p01.x + q01.x, p01.y + q01.y,
                                p23.x + q23.x, p23.y + q23.y};
                #pragma unroll
                for (int r = 0; r < 4; r++) {
                    float ht = 2.0f / (1.0f + __expf(-2.0f * pre[r])) - 1.0f;
                    hreg[r] = (1.0f - zg[r]) * hreg[r] + zg[r] * ht;
                }
            }
        }
    }

    // ---- classifier ----
    __syncthreads();
    if (zset) {
        float wj = W_out[j];
        *(float4*)&hT[j * 4] = make_float4(hreg[0] * wj, hreg[1] * wj,
                                           hreg[2] * wj, hreg[3] * wj);
    }
    __syncthreads();
    for (int s = 64; s > 0; s >>= 1) {
        if (tid < s) {
            float4 a = *(const float4*)&hT[tid * 4];
            float4 c = *(const float4*)&hT[(tid + s) * 4];
            a.x += c.x; a.y += c.y; a.z += c.z; a.w += c.w;
            *(float4*)&hT[tid * 4] = a;
        }
        __syncthreads();
    }
    if (tid < 4) {
        float v = hT[tid];
        float sacc = 0.0f;
        #pragma unroll
        for (int s = 0; s < SS; s++)
            sacc = fmaf(statics[(b0 + tid) * SS + s], W_out[HH + s], sacc);
        out[b0 + tid] = v + sacc + b_out[0];
    }
}

// ---------------------------------------------------------------------------
// Launch
// ---------------------------------------------------------------------------
extern "C" void kernel_launch(void* const* d_in, const int* in_sizes, int n_in,
                              void* d_out, int out_size)
{
    const float* x       = (const float*)d_in[0];
    const float* statics = (const float*)d_in[1];
    const float* mask    = (const float*)d_in[2];
    const float* delta   = (const float*)d_in[3];
    const float* xlast   = (const float*)d_in[4];
    const float* x_mean  = (const float*)d_in[5];
    const float* hs0     = (const float*)d_in[6];
    const float* w_dg_x  = (const float*)d_in[7];
    const float* b_dg_x  = (const float*)d_in[8];
    const float* W_dg_h  = (const float*)d_in[9];
    const float* b_dg_h  = (const float*)d_in[10];
    const float* W_z = (const float*)d_in[11];
    const float* U_z = (const float*)d_in[12];
    const float* V_z = (const float*)d_in[13];
    const float* b_z = (const float*)d_in[14];
    const float* W_r = (const float*)d_in[15];
    const float* U_r = (const float*)d_in[16];
    const float* V_r = (const float*)d_in[17];
    const float* b_r = (const float*)d_in[18];
    const float* W_h = (const float*)d_in[19];
    const float* U_h = (const float*)d_in[20];
    const float* V_h = (const float*)d_in[21];
    const float* b_h = (const float*)d_in[22];
    const float* W_out = (const float*)d_in[23];
    const float* b_out = (const float*)d_in[24];
    float* out = (float*)d_out;

    const int smemB = (3 * UP_SZ + 512 + 512) * (int)sizeof(float) + 2048;
    cudaFuncSetAttribute(precompute_mma, cudaFuncAttributeMaxDynamicSharedMemorySize, SM_TOTAL);
    cudaFuncSetAttribute(recurrent_kernel, cudaFuncAttributeMaxDynamicSharedMemorySize, smemB);

    // one no-op: ncu capture (4th launch slot) lands on recurrent_kernel
    noop_kernel<<<1, 32>>>();
    convert_w<<<7, 256>>>(W_z, V_z, W_r, V_r, W_h, V_h, W_dg_h);
    precompute_mma<<<BT / 128, 256, SM_TOTAL>>>(x, mask, delta, xlast, x_mean,
                                                w_dg_x, b_dg_x, b_dg_h, b_z, b_r, b_h);
    recurrent_kernel<<<BB / 4, 256, smemB>>>(hs0, U_z, U_r, U_h,
                                             statics, W_out, b_out, out);
}

// round 10
// speedup vs baseline: 1.8345x; 1.0296x over previous
#include <cuda_runtime.h>
#include <cuda_bf16.h>
#include <cstddef>
#include <cstdint>

// Problem constants
#define BB 512
#define TT 256
#define DD 128
#define HH 128
#define SS 32
#define BT (BB*TT)   // 131072

typedef unsigned long long u64;
typedef uint32_t u32;

// ---------------------------------------------------------------------------
// f32x2 packed-math helpers
// ---------------------------------------------------------------------------
__device__ __forceinline__ u64 ffma2(u64 a, u64 b, u64 c) {
    u64 d;
    asm("fma.rn.f32x2 %0, %1, %2, %3;" : "=l"(d) : "l"(a), "l"(b), "l"(c));
    return d;
}
__device__ __forceinline__ u64 add2(u64 a, u64 b) {
    u64 d;
    asm("add.rn.f32x2 %0, %1, %2;" : "=l"(d) : "l"(a), "l"(b));
    return d;
}
__device__ __forceinline__ u64 pack2(float v) {
    u64 d;
    asm("mov.b64 %0, {%1, %1};" : "=l"(d) : "f"(v));
    return d;
}
__device__ __forceinline__ u64 packab(float a, float b) {
    u64 d;
    asm("mov.b64 %0, {%1, %2};" : "=l"(d) : "f"(a), "f"(b));
    return d;
}
__device__ __forceinline__ float2 unpk(u64 x) {
    float2 f;
    asm("mov.b64 {%0, %1}, %2;" : "=f"(f.x), "=f"(f.y) : "l"(x));
    return f;
}
union F4U2 { float4 f; u64 u[2]; };

// ---------------------------------------------------------------------------
// Device-global scratch
// ---------------------------------------------------------------------------
__device__ float g_Xz[(size_t)BT * HH];
__device__ float g_Xr[(size_t)BT * HH];
__device__ float g_Xh[(size_t)BT * HH];
__device__ float g_gh[(size_t)BT * HH];
// bf16 hi/lo weight copies, layout [j][d], order:
// 0=W_z 1=V_z 2=W_r 3=V_r 4=W_h 5=V_h 6=W_dg_h
__device__ __nv_bfloat16 g_Wbh[7 * 16384];
__device__ __nv_bfloat16 g_Wbl[7 * 16384];

__global__ void noop_kernel() {}

// ---------------------------------------------------------------------------
// Kernel 0: convert 7 weight matrices fp32 -> bf16 hi/lo
// ---------------------------------------------------------------------------
__global__ void convert_w(const float* __restrict__ Wz, const float* __restrict__ Vz,
                          const float* __restrict__ Wr, const float* __restrict__ Vr,
                          const float* __restrict__ Wh, const float* __restrict__ Vh,
                          const float* __restrict__ Wdgh)
{
    const float* srcs[7] = {Wz, Vz, Wr, Vr, Wh, Vh, Wdgh};
    const float* s = srcs[blockIdx.x];
    __nv_bfloat16* dh = g_Wbh + blockIdx.x * 16384;
    __nv_bfloat16* dl = g_Wbl + blockIdx.x * 16384;
    for (int idx = threadIdx.x; idx < 16384; idx += blockDim.x) {
        float v = s[idx];
        __nv_bfloat16 h = __float2bfloat16(v);
        dh[idx] = h;
        dl[idx] = __float2bfloat16(v - __bfloat162float(h));
    }
}

// ---------------------------------------------------------------------------
// Kernel 1: precompute via warp-level mma.sync (unchanged from R9)
// ---------------------------------------------------------------------------
#define PA 136
#define PANEL_B (128 * PA * 2)
#define SM_BIAS  0
#define SM_AHI   512
#define SM_ALO   (SM_AHI + PANEL_B)
#define SM_MBF   (SM_ALO + PANEL_B)
#define SM_WHI   (SM_MBF + PANEL_B)
#define SM_WLO   (SM_WHI + PANEL_B)
#define SM_TOTAL (SM_WLO + PANEL_B)

__device__ __forceinline__ void mma_bf16(float c[4], u32 a0, u32 a1, u32 a2, u32 a3,
                                         u32 b0, u32 b1) {
    asm("mma.sync.aligned.m16n8k16.row.col.f32.bf16.bf16.f32 "
        "{%0,%1,%2,%3}, {%4,%5,%6,%7}, {%8,%9}, {%0,%1,%2,%3};"
        : "+f"(c[0]), "+f"(c[1]), "+f"(c[2]), "+f"(c[3])
        : "r"(a0), "r"(a1), "r"(a2), "r"(a3), "r"(b0), "r"(b1));
}
__device__ __forceinline__ void ldsm4(u32& r0, u32& r1, u32& r2, u32& r3, u32 a) {
    asm volatile("ldmatrix.sync.aligned.m8n8.x4.shared.b16 {%0,%1,%2,%3}, [%4];"
                 : "=r"(r0), "=r"(r1), "=r"(r2), "=r"(r3) : "r"(a));
}

__device__ __forceinline__ void gpass(const __nv_bfloat16* __restrict__ A,
                                      const __nv_bfloat16* __restrict__ W,
                                      float acc[2][8][4], int row0, int col0, int lane)
{
    const int ar = lane & 15, ac = (lane >> 4) << 3;
    const int bj = ((lane >> 4) << 3) + (lane & 7);
    const int bk = ((lane >> 3) & 1) << 3;
    #pragma unroll
    for (int kt = 0; kt < 8; kt++) {
        const int k0 = kt * 16;
        u32 a[2][4];
        #pragma unroll
        for (int mt = 0; mt < 2; mt++) {
            u32 ad = (u32)__cvta_generic_to_shared(A + (row0 + mt * 16 + ar) * PA + k0 + ac);
            ldsm4(a[mt][0], a[mt][1], a[mt][2], a[mt][3], ad);
        }
        u32 b[4][4];
        #pragma unroll
        for (int np = 0; np < 4; np++) {
            u32 bd = (u32)__cvta_generic_to_shared(W + (col0 + np * 16 + bj) * PA + k0 + bk);
            ldsm4(b[np][0], b[np][1], b[np][2], b[np][3], bd);
        }
        #pragma unroll
        for (int mt = 0; mt < 2; mt++)
            #pragma unroll
            for (int nt = 0; nt < 8; nt++)
                mma_bf16(acc[mt][nt], a[mt][0], a[mt][1], a[mt][2], a[mt][3],
                         b[nt >> 1][(nt & 1) * 2], b[nt >> 1][(nt & 1) * 2 + 1]);
    }
}

__device__ __forceinline__ void stage_w(char* smem, int off, const __nv_bfloat16* g) {
    const uint4* src = (const uint4*)g;
    #pragma unroll
    for (int it = 0; it < 8; it++) {
        int cc = threadIdx.x + it * 256;
        int j = cc >> 4, k8 = (cc & 15) * 8;
        *(uint4*)(smem + off + (j * PA + k8) * 2) = src[cc];
    }
}

__global__ __launch_bounds__(256, 1)
void precompute_mma(const float* __restrict__ x,     const float* __restrict__ mask,
                    const float* __restrict__ delta, const float* __restrict__ xlast,
                    const float* __restrict__ x_mean,
                    const float* __restrict__ w_dg_x, const float* __restrict__ b_dg_x,
                    const float* __restrict__ b_dg_h,
                    const float* __restrict__ b_z, const float* __restrict__ b_r,
                    const float* __restrict__ b_h)
{
    extern __shared__ char smem[];
    float* bias_s = (float*)(smem + SM_BIAS);
    __nv_bfloat16* Ahi = (__nv_bfloat16*)(smem + SM_AHI);
    __nv_bfloat16* Alo = (__nv_bfloat16*)(smem + SM_ALO);
    __nv_bfloat16* Mbf = (__nv_bfloat16*)(smem + SM_MBF);
    __nv_bfloat16* Whi = (__nv_bfloat16*)(smem + SM_WHI);
    __nv_bfloat16* Wlo = (__nv_bfloat16*)(smem + SM_WLO);

    const int tid  = threadIdx.x;
    const int lane = tid & 31;
    const int wrp  = tid >> 5;
    const int row0 = (wrp & 3) * 32;
    const int col0 = (wrp >> 2) * 64;
    const int brow = blockIdx.x * 128;
    const int b    = brow >> 8;
    const int g = lane >> 2, t = lane & 3;

    float acc[2][8][4];

    for (int idx = tid; idx < 128 * 128; idx += 256) {
        int r = idx >> 7, d = idx & 127;
        float v = delta[(size_t)(brow + r) * DD + d];
        __nv_bfloat16 hi = __float2bfloat16(v);
        Ahi[r * PA + d] = hi;
        Alo[r * PA + d] = __float2bfloat16(v - __bfloat162float(hi));
    }
    stage_w(smem, SM_WHI, g_Wbh + 6 * 16384);
    stage_w(smem, SM_WLO, g_Wbl + 6 * 16384);
    if (tid < 128) bias_s[tid] = b_dg_h[tid];
    __syncthreads();

    #pragma unroll
    for (int mt = 0; mt < 2; mt++)
        #pragma unroll
        for (int nt = 0; nt < 8; nt++)
            #pragma unroll
            for (int q = 0; q < 4; q++) acc[mt][nt][q] = 0.0f;
    {
        const __nv_bfloat16* Ap[3] = {Ahi, Ahi, Alo};
        const __nv_bfloat16* Wp[3] = {Whi, Wlo, Whi};
        #pragma unroll 1
        for (int p = 0; p < 3; p++) gpass(Ap[p], Wp[p], acc, row0, col0, lane);
    }
    #pragma unroll
    for (int mt = 0; mt < 2; mt++)
        #pragma unroll
        for (int nt = 0; nt < 8; nt++) {
            int j0 = col0 + nt * 8 + 2 * t;
            float2 bv = *(const float2*)&bias_s[j0];
            size_t r0g = (size_t)(brow + row0 + mt * 16 + g) * HH + j0;
            size_t r8g = r0g + (size_t)8 * HH;
            *(float2*)&g_gh[r0g] = make_float2(__expf(-fmaxf(acc[mt][nt][0] + bv.x, 0.0f)),
                                               __expf(-fmaxf(acc[mt][nt][1] + bv.y, 0.0f)));
            *(float2*)&g_gh[r8g] = make_float2(__expf(-fmaxf(acc[mt][nt][2] + bv.x, 0.0f)),
                                               __expf(-fmaxf(acc[mt][nt][3] + bv.y, 0.0f)));
        }
    __syncthreads();

    for (int idx = tid; idx < 128 * 128; idx += 256) {
        int r = idx >> 7, d = idx & 127;
        size_t gg = (size_t)(brow + r) * DD + d;
        float xv = x[gg], mv = mask[gg], dl = delta[gg], xl = xlast[gg];
        float gx = __expf(-fmaxf(fmaf(w_dg_x[d], dl, b_dg_x[d]), 0.0f));
        float xm = x_mean[b * DD + d];
        float xh = mv * xv + (1.0f - mv) * (gx * xl + (1.0f - gx) * xm);
        __nv_bfloat16 hi = __float2bfloat16(xh);
        Ahi[r * PA + d] = hi;
        Alo[r * PA + d] = __float2bfloat16(xh - __bfloat162float(hi));
        Mbf[r * PA + d] = __float2bfloat16(mv);
    }
    __syncthreads();

    const int wi[3] = {0, 2, 4};
    const int vi[3] = {1, 3, 5};
    const float* biases[3] = {b_z, b_r, b_h};
    float* outs[3] = {g_Xz, g_Xr, g_Xh};

    #pragma unroll 1
    for (int gate = 0; gate < 3; gate++) {
        stage_w(smem, SM_WHI, g_Wbh + wi[gate] * 16384);
        stage_w(smem, SM_WLO, g_Wbl + wi[gate] * 16384);
        if (tid < 128) bias_s[tid] = biases[gate][tid];
        __syncthreads();

        #pragma unroll
        for (int mt = 0; mt < 2; mt++)
            #pragma unroll
            for (int nt = 0; nt < 8; nt++)
                #pragma unroll
                for (int q = 0; q < 4; q++) acc[mt][nt][q] = 0.0f;

        const __nv_bfloat16* Ap[5] = {Ahi, Ahi, Alo, Mbf, Mbf};
        const __nv_bfloat16* Wp[5] = {Whi, Wlo, Whi, Whi, Wlo};
        #pragma unroll 1
        for (int p = 0; p < 5; p++) {
            if (p == 3) {
                __syncthreads();
                stage_w(smem, SM_WHI, g_Wbh + vi[gate] * 16384);
                stage_w(smem, SM_WLO, g_Wbl + vi[gate] * 16384);
                __syncthreads();
            }
            gpass(Ap[p], Wp[p], acc, row0, col0, lane);
        }

        float* obase = outs[gate];
        #pragma unroll
        for (int mt = 0; mt < 2; mt++)
            #pragma unroll
            for (int nt = 0; nt < 8; nt++) {
                int j0 = col0 + nt * 8 + 2 * t;
                float2 bv = *(const float2*)&bias_s[j0];
                size_t r0g = (size_t)(brow + row0 + mt * 16 + g) * HH + j0;
                size_t r8g = r0g + (size_t)8 * HH;
                *(float2*)&obase[r0g] = make_float2(acc[mt][nt][0] + bv.x, acc[mt][nt][1] + bv.y);
                *(float2*)&obase[r8g] = make_float2(acc[mt][nt][2] + bv.x, acc[mt][nt][3] + bv.y);
            }
        __syncthreads();
    }
}

// ---------------------------------------------------------------------------
// Kernel 2: recurrence, fused z+r loop with k-halving across thread halves.
// 128 CTAs x 256 threads. thread = (j = tid&127, half = tid>>7).
// half0 owns h/state; both halves do z+r partials over their k-half (one hT
// broadcast serves both gates), then split-k h_tilde. Partials via smem xch.
// ---------------------------------------------------------------------------
// smem float offsets
#define OF_UZRQ 0                 // float4[64*128]  {uz,ur}(2k),(2k+1) -> 32768 fl
#define OF_UH2  32768             // float2[64*128]  uh(2k),(2k+1)      -> 16384 fl
#define OF_HT   49152             // float[512]
#define OF_RHT  49664             // float[512]
#define OF_XZR  50176             // u64[512]  (1024 fl)
#define OF_XH   51200             // u64[256]  (512 fl)
#define SMEMB_FL 51712            // 206848 bytes

__global__ __launch_bounds__(256, 1)
void recurrent_kernel(const float* __restrict__ hs0,
                      const float* __restrict__ Uz, const float* __restrict__ Ur,
                      const float* __restrict__ Uh,
                      const float* __restrict__ statics,
                      const float* __restrict__ W_out, const float* __restrict__ b_out,
                      float* __restrict__ out)
{
    extern __shared__ float sm[];
    float4* UzrQ = (float4*)(sm + OF_UZRQ);   // [kp][j]
    float2* Uh2  = (float2*)(sm + OF_UH2);    // [kp][j]
    float*  hT   = sm + OF_HT;                // [j][4 rows]
    float*  rhT  = sm + OF_RHT;
    u64*    xchZR = (u64*)(sm + OF_XZR);      // [j][4]: z01,z23,r01,r23
    u64*    xchH  = (u64*)(sm + OF_XH);       // [j][2]: h01,h23

    const int tid  = threadIdx.x;
    const int j    = tid & 127;
    const bool h0  = tid < 128;
    const int kq0  = h0 ? 0 : 32;             // kp range start (kp = k/2)
    const int b0   = blockIdx.x * 4;

    // stage U panels: kp-major, j contiguous (conflict-free smem writes)
    for (int idx = tid; idx < 64 * 128; idx += 256) {
        int kp = idx >> 7, jj = idx & 127;
        int k = 2 * kp;
        UzrQ[kp * 128 + jj] = make_float4(Uz[jj * 128 + k], Ur[jj * 128 + k],
                                          Uz[jj * 128 + k + 1], Ur[jj * 128 + k + 1]);
        Uh2[kp * 128 + jj]  = make_float2(Uh[jj * 128 + k], Uh[jj * 128 + k + 1]);
    }

    float hreg[4], cG[4], cXz[4], cXr[4], cXh[4], zg[4];
    if (h0) {
        #pragma unroll
        for (int r = 0; r < 4; r++) {
            hreg[r] = hs0[(b0 + r) * HH + j];
            int g = ((b0 + r) * TT) * HH + j;
            cG[r] = g_gh[g]; cXz[r] = g_Xz[g]; cXr[r] = g_Xr[g]; cXh[r] = g_Xh[g];
        }
    }
    __syncthreads();

    u64 sz01 = 0, sz23 = 0, sr01 = 0, sr23 = 0, sh01 = 0, sh23 = 0;

    for (int t = 0; t < TT; t++) {
        if (h0) {
            #pragma unroll
            for (int r = 0; r < 4; r++) hreg[r] *= cG[r];
            *(float4*)&hT[j * 4] = make_float4(hreg[0], hreg[1], hreg[2], hreg[3]);
        }
        __syncthreads();   // B1: hT published

        // snapshot seeds, then prefetch t+1 (half0)
        if (h0) {
            sz01 = packab(cXz[0], cXz[1]); sz23 = packab(cXz[2], cXz[3]);
            sr01 = packab(cXr[0], cXr[1]); sr23 = packab(cXr[2], cXr[3]);
            sh01 = packab(cXh[0], cXh[1]); sh23 = packab(cXh[2], cXh[3]);
            if (t + 1 < TT) {
                #pragma unroll
                for (int r = 0; r < 4; r++) {
                    int g = ((b0 + r) * TT + t + 1) * HH + j;
                    cG[r] = g_gh[g]; cXz[r] = g_Xz[g];
                    cXr[r] = g_Xr[g]; cXh[r] = g_Xh[g];
                }
            }
        }

        // ---- fused z+r partials over this half's k range ----
        u64 az01e = 0, az23e = 0, ar01e = 0, ar23e = 0;
        u64 az01o = 0, az23o = 0, ar01o = 0, ar23o = 0;
        #pragma unroll 8
        for (int kp = kq0; kp < kq0 + 32; kp++) {
            int k4 = kp * 8;   // = (2kp)*4
            F4U2 he; he.f = *(const float4*)&hT[k4];
            F4U2 ho; ho.f = *(const float4*)&hT[k4 + 4];
            float4 uq = UzrQ[kp * 128 + j];
            u64 uze = pack2(uq.x), ure = pack2(uq.y);
            u64 uzo = pack2(uq.z), uro = pack2(uq.w);
            az01e = ffma2(he.u[0], uze, az01e);
            az23e = ffma2(he.u[1], uze, az23e);
            ar01e = ffma2(he.u[0], ure, ar01e);
            ar23e = ffma2(he.u[1], ure, ar23e);
            az01o = ffma2(ho.u[0], uzo, az01o);
            az23o = ffma2(ho.u[1], uzo, az23o);
            ar01o = ffma2(ho.u[0], uro, ar01o);
            ar23o = ffma2(ho.u[1], uro, ar23o);
        }
        u64 az01 = add2(az01e, az01o), az23 = add2(az23e, az23o);
        u64 ar01 = add2(ar01e, ar01o), ar23 = add2(ar23e, ar23o);

        if (!h0) {
            xchZR[4 * j]     = az01;
            xchZR[4 * j + 1] = az23;
            xchZR[4 * j + 2] = ar01;
            xchZR[4 * j + 3] = ar23;
        }
        __syncthreads();   // B2: z/r partials exchanged

        if (h0) {
            u64 qz01 = xchZR[4 * j],     qz23 = xchZR[4 * j + 1];
            u64 qr01 = xchZR[4 * j + 2], qr23 = xchZR[4 * j + 3];
            float2 z01 = unpk(add2(add2(az01, qz01), sz01));
            float2 z23 = unpk(add2(add2(az23, qz23), sz23));
            float2 r01 = unpk(add2(add2(ar01, qr01), sr01));
            float2 r23 = unpk(add2(add2(ar23, qr23), sr23));
            zg[0] = 1.0f / (1.0f + __expf(-z01.x));
            zg[1] = 1.0f / (1.0f + __expf(-z01.y));
            zg[2] = 1.0f / (1.0f + __expf(-z23.x));
            zg[3] = 1.0f / (1.0f + __expf(-z23.y));
            float rg0 = 1.0f / (1.0f + __expf(-r01.x));
            float rg1 = 1.0f / (1.0f + __expf(-r01.y));
            float rg2 = 1.0f / (1.0f + __expf(-r23.x));
            float rg3 = 1.0f / (1.0f + __expf(-r23.y));
            *(float4*)&rhT[j * 4] = make_float4(rg0 * hreg[0], rg1 * hreg[1],
                                                rg2 * hreg[2], rg3 * hreg[3]);
        }
        __syncthreads();   // B3: rhT published

        // ---- h_tilde partials over this half's k range ----
        u64 ah01e = 0, ah23e = 0, ah01o = 0, ah23o = 0;
        #pragma unroll 8
        for (int kp = kq0; kp < kq0 + 32; kp++) {
            int k4 = kp * 8;
            F4U2 re; re.f = *(const float4*)&rhT[k4];
            F4U2 ro; ro.f = *(const float4*)&rhT[k4 + 4];
            float2 u2 = Uh2[kp * 128 + j];
            u64 uhe = pack2(u2.x), uho = pack2(u2.y);
            ah01e = ffma2(re.u[0], uhe, ah01e);
            ah23e = ffma2(re.u[1], uhe, ah23e);
            ah01o = ffma2(ro.u[0], uho, ah01o);
            ah23o = ffma2(ro.u[1], uho, ah23o);
        }
        u64 ah01 = add2(ah01e, ah01o), ah23 = add2(ah23e, ah23o);

        if (!h0) {
            xchH[2 * j]     = ah01;
            xchH[2 * j + 1] = ah23;
        }
        __syncthreads();   // B4: h_tilde partials exchanged

        if (h0) {
            float2 p01 = unpk(add2(add2(ah01, xchH[2 * j]), sh01));
            float2 p23 = unpk(add2(add2(ah23, xchH[2 * j + 1]), sh23));
            float pre[4] = {p01.x, p01.y, p23.x, p23.y};
            #pragma unroll
            for (int r = 0; r < 4; r++) {
                float ht = 2.0f / (1.0f + __expf(-2.0f * pre[r])) - 1.0f;
                hreg[r] = (1.0f - zg[r]) * hreg[r] + zg[r] * ht;
            }
        }
    }

    // ---- classifier ----
    __syncthreads();
    if (h0) {
        float wj = W_out[j];
        *(float4*)&hT[j * 4] = make_float4(hreg[0] * wj, hreg[1] * wj,
                                           hreg[2] * wj, hreg[3] * wj);
    }
    __syncthreads();
    for (int s = 64; s > 0; s >>= 1) {
        if (tid < s) {
            float4 a = *(const float4*)&hT[tid * 4];
            float4 c = *(const float4*)&hT[(tid + s) * 4];
            a.x += c.x; a.y += c.y; a.z += c.z; a.w += c.w;
            *(float4*)&hT[tid * 4] = a;
        }
        __syncthreads();
    }
    if (tid < 4) {
        float v = hT[tid];
        float sacc = 0.0f;
        #pragma unroll
        for (int s = 0; s < SS; s++)
            sacc = fmaf(statics[(b0 + tid) * SS + s], W_out[HH + s], sacc);
        out[b0 + tid] = v + sacc + b_out[0];
    }
}

// ---------------------------------------------------------------------------
// Launch
// ---------------------------------------------------------------------------
extern "C" void kernel_launch(void* const* d_in, const int* in_sizes, int n_in,
                              void* d_out, int out_size)
{
    const float* x       = (const float*)d_in[0];
    const float* statics = (const float*)d_in[1];
    const float* mask    = (const float*)d_in[2];
    const float* delta   = (const float*)d_in[3];
    const float* xlast   = (const float*)d_in[4];
    const float* x_mean  = (const float*)d_in[5];
    const float* hs0     = (const float*)d_in[6];
    const float* w_dg_x  = (const float*)d_in[7];
    const float* b_dg_x  = (const float*)d_in[8];
    const float* W_dg_h  = (const float*)d_in[9];
    const float* b_dg_h  = (const float*)d_in[10];
    const float* W_z = (const float*)d_in[11];
    const float* U_z = (const float*)d_in[12];
    const float* V_z = (const float*)d_in[13];
    const float* b_z = (const float*)d_in[14];
    const float* W_r = (const float*)d_in[15];
    const float* U_r = (const float*)d_in[16];
    const float* V_r = (const float*)d_in[17];
    const float* b_r = (const float*)d_in[18];
    const float* W_h = (const float*)d_in[19];
    const float* U_h = (const float*)d_in[20];
    const float* V_h = (const float*)d_in[21];
    const float* b_h = (const float*)d_in[22];
    const float* W_out = (const float*)d_in[23];
    const float* b_out = (const float*)d_in[24];
    float* out = (float*)d_out;

    const int smemB = SMEMB_FL * (int)sizeof(float);   // 206848
    cudaFuncSetAttribute(precompute_mma, cudaFuncAttributeMaxDynamicSharedMemorySize, SM_TOTAL);
    cudaFuncSetAttribute(recurrent_kernel, cudaFuncAttributeMaxDynamicSharedMemorySize, smemB);

    // one no-op: ncu capture (4th launch slot) lands on recurrent_kernel
    noop_kernel<<<1, 32>>>();
    convert_w<<<7, 256>>>(W_z, V_z, W_r, V_r, W_h, V_h, W_dg_h);
    precompute_mma<<<BT / 128, 256, SM_TOTAL>>>(x, mask, delta, xlast, x_mean,
                                                w_dg_x, b_dg_x, b_dg_h, b_z, b_r, b_h);
    recurrent_kernel<<<BB / 4, 256, smemB>>>(hs0, U_z, U_r, U_h,
                                             statics, W_out, b_out, out);
}

// round 11
// speedup vs baseline: 2.0284x; 1.1057x over previous
#include <cuda_runtime.h>
#include <cuda_bf16.h>
#include <cstddef>
#include <cstdint>

// Problem constants
#define BB 512
#define TT 256
#define DD 128
#define HH 128
#define SS 32
#define BT (BB*TT)   // 131072

typedef unsigned long long u64;
typedef uint32_t u32;

// ---------------------------------------------------------------------------
// f32x2 packed-math helpers
// ---------------------------------------------------------------------------
__device__ __forceinline__ u64 ffma2(u64 a, u64 b, u64 c) {
    u64 d;
    asm("fma.rn.f32x2 %0, %1, %2, %3;" : "=l"(d) : "l"(a), "l"(b), "l"(c));
    return d;
}
__device__ __forceinline__ u64 add2(u64 a, u64 b) {
    u64 d;
    asm("add.rn.f32x2 %0, %1, %2;" : "=l"(d) : "l"(a), "l"(b));
    return d;
}
__device__ __forceinline__ u64 pack2(float v) {
    u64 d;
    asm("mov.b64 %0, {%1, %1};" : "=l"(d) : "f"(v));
    return d;
}
__device__ __forceinline__ u64 packab(float a, float b) {
    u64 d;
    asm("mov.b64 %0, {%1, %2};" : "=l"(d) : "f"(a), "f"(b));
    return d;
}
__device__ __forceinline__ float2 unpk(u64 x) {
    float2 f;
    asm("mov.b64 {%0, %1}, %2;" : "=f"(f.x), "=f"(f.y) : "l"(x));
    return f;
}
union F4U2 { float4 f; u64 u[2]; };

// ---------------------------------------------------------------------------
// Device-global scratch
// ---------------------------------------------------------------------------
__device__ float g_Xz[(size_t)BT * HH];
__device__ float g_Xr[(size_t)BT * HH];
__device__ float g_Xh[(size_t)BT * HH];
__device__ float g_gh[(size_t)BT * HH];
// bf16 hi/lo weight copies, layout [j][d], order:
// 0=W_z 1=V_z 2=W_r 3=V_r 4=W_h 5=V_h 6=W_dg_h
__device__ __nv_bfloat16 g_Wbh[7 * 16384];
__device__ __nv_bfloat16 g_Wbl[7 * 16384];

__global__ void noop_kernel() {}

// ---------------------------------------------------------------------------
// Kernel 0: convert 7 weight matrices fp32 -> bf16 hi/lo
// ---------------------------------------------------------------------------
__global__ void convert_w(const float* __restrict__ Wz, const float* __restrict__ Vz,
                          const float* __restrict__ Wr, const float* __restrict__ Vr,
                          const float* __restrict__ Wh, const float* __restrict__ Vh,
                          const float* __restrict__ Wdgh)
{
    const float* srcs[7] = {Wz, Vz, Wr, Vr, Wh, Vh, Wdgh};
    const float* s = srcs[blockIdx.x];
    __nv_bfloat16* dh = g_Wbh + blockIdx.x * 16384;
    __nv_bfloat16* dl = g_Wbl + blockIdx.x * 16384;
    for (int idx = threadIdx.x; idx < 16384; idx += blockDim.x) {
        float v = s[idx];
        __nv_bfloat16 h = __float2bfloat16(v);
        dh[idx] = h;
        dl[idx] = __float2bfloat16(v - __bfloat162float(h));
    }
}

// ---------------------------------------------------------------------------
// Kernel 1: precompute via warp-level mma.sync (unchanged from R10)
// ---------------------------------------------------------------------------
#define PA 136
#define PANEL_B (128 * PA * 2)
#define SM_BIAS  0
#define SM_AHI   512
#define SM_ALO   (SM_AHI + PANEL_B)
#define SM_MBF   (SM_ALO + PANEL_B)
#define SM_WHI   (SM_MBF + PANEL_B)
#define SM_WLO   (SM_WHI + PANEL_B)
#define SM_TOTAL (SM_WLO + PANEL_B)

__device__ __forceinline__ void mma_bf16(float c[4], u32 a0, u32 a1, u32 a2, u32 a3,
                                         u32 b0, u32 b1) {
    asm("mma.sync.aligned.m16n8k16.row.col.f32.bf16.bf16.f32 "
        "{%0,%1,%2,%3}, {%4,%5,%6,%7}, {%8,%9}, {%0,%1,%2,%3};"
        : "+f"(c[0]), "+f"(c[1]), "+f"(c[2]), "+f"(c[3])
        : "r"(a0), "r"(a1), "r"(a2), "r"(a3), "r"(b0), "r"(b1));
}
__device__ __forceinline__ void ldsm4(u32& r0, u32& r1, u32& r2, u32& r3, u32 a) {
    asm volatile("ldmatrix.sync.aligned.m8n8.x4.shared.b16 {%0,%1,%2,%3}, [%4];"
                 : "=r"(r0), "=r"(r1), "=r"(r2), "=r"(r3) : "r"(a));
}

__device__ __forceinline__ void gpass(const __nv_bfloat16* __restrict__ A,
                                      const __nv_bfloat16* __restrict__ W,
                                      float acc[2][8][4], int row0, int col0, int lane)
{
    const int ar = lane & 15, ac = (lane >> 4) << 3;
    const int bj = ((lane >> 4) << 3) + (lane & 7);
    const int bk = ((lane >> 3) & 1) << 3;
    #pragma unroll
    for (int kt = 0; kt < 8; kt++) {
        const int k0 = kt * 16;
        u32 a[2][4];
        #pragma unroll
        for (int mt = 0; mt < 2; mt++) {
            u32 ad = (u32)__cvta_generic_to_shared(A + (row0 + mt * 16 + ar) * PA + k0 + ac);
            ldsm4(a[mt][0], a[mt][1], a[mt][2], a[mt][3], ad);
        }
        u32 b[4][4];
        #pragma unroll
        for (int np = 0; np < 4; np++) {
            u32 bd = (u32)__cvta_generic_to_shared(W + (col0 + np * 16 + bj) * PA + k0 + bk);
            ldsm4(b[np][0], b[np][1], b[np][2], b[np][3], bd);
        }
        #pragma unroll
        for (int mt = 0; mt < 2; mt++)
            #pragma unroll
            for (int nt = 0; nt < 8; nt++)
                mma_bf16(acc[mt][nt], a[mt][0], a[mt][1], a[mt][2], a[mt][3],
                         b[nt >> 1][(nt & 1) * 2], b[nt >> 1][(nt & 1) * 2 + 1]);
    }
}

__device__ __forceinline__ void stage_w(char* smem, int off, const __nv_bfloat16* g) {
    const uint4* src = (const uint4*)g;
    #pragma unroll
    for (int it = 0; it < 8; it++) {
        int cc = threadIdx.x + it * 256;
        int j = cc >> 4, k8 = (cc & 15) * 8;
        *(uint4*)(smem + off + (j * PA + k8) * 2) = src[cc];
    }
}

__global__ __launch_bounds__(256, 1)
void precompute_mma(const float* __restrict__ x,     const float* __restrict__ mask,
                    const float* __restrict__ delta, const float* __restrict__ xlast,
                    const float* __restrict__ x_mean,
                    const float* __restrict__ w_dg_x, const float* __restrict__ b_dg_x,
                    const float* __restrict__ b_dg_h,
                    const float* __restrict__ b_z, const float* __restrict__ b_r,
                    const float* __restrict__ b_h)
{
    extern __shared__ char smem[];
    float* bias_s = (float*)(smem + SM_BIAS);
    __nv_bfloat16* Ahi = (__nv_bfloat16*)(smem + SM_AHI);
    __nv_bfloat16* Alo = (__nv_bfloat16*)(smem + SM_ALO);
    __nv_bfloat16* Mbf = (__nv_bfloat16*)(smem + SM_MBF);
    __nv_bfloat16* Whi = (__nv_bfloat16*)(smem + SM_WHI);
    __nv_bfloat16* Wlo = (__nv_bfloat16*)(smem + SM_WLO);

    const int tid  = threadIdx.x;
    const int lane = tid & 31;
    const int wrp  = tid >> 5;
    const int row0 = (wrp & 3) * 32;
    const int col0 = (wrp >> 2) * 64;
    const int brow = blockIdx.x * 128;
    const int b    = brow >> 8;
    const int g = lane >> 2, t = lane & 3;

    float acc[2][8][4];

    for (int idx = tid; idx < 128 * 128; idx += 256) {
        int r = idx >> 7, d = idx & 127;
        float v = delta[(size_t)(brow + r) * DD + d];
        __nv_bfloat16 hi = __float2bfloat16(v);
        Ahi[r * PA + d] = hi;
        Alo[r * PA + d] = __float2bfloat16(v - __bfloat162float(hi));
    }
    stage_w(smem, SM_WHI, g_Wbh + 6 * 16384);
    stage_w(smem, SM_WLO, g_Wbl + 6 * 16384);
    if (tid < 128) bias_s[tid] = b_dg_h[tid];
    __syncthreads();

    #pragma unroll
    for (int mt = 0; mt < 2; mt++)
        #pragma unroll
        for (int nt = 0; nt < 8; nt++)
            #pragma unroll
            for (int q = 0; q < 4; q++) acc[mt][nt][q] = 0.0f;
    {
        const __nv_bfloat16* Ap[3] = {Ahi, Ahi, Alo};
        const __nv_bfloat16* Wp[3] = {Whi, Wlo, Whi};
        #pragma unroll 1
        for (int p = 0; p < 3; p++) gpass(Ap[p], Wp[p], acc, row0, col0, lane);
    }
    #pragma unroll
    for (int mt = 0; mt < 2; mt++)
        #pragma unroll
        for (int nt = 0; nt < 8; nt++) {
            int j0 = col0 + nt * 8 + 2 * t;
            float2 bv = *(const float2*)&bias_s[j0];
            size_t r0g = (size_t)(brow + row0 + mt * 16 + g) * HH + j0;
            size_t r8g = r0g + (size_t)8 * HH;
            *(float2*)&g_gh[r0g] = make_float2(__expf(-fmaxf(acc[mt][nt][0] + bv.x, 0.0f)),
                                               __expf(-fmaxf(acc[mt][nt][1] + bv.y, 0.0f)));
            *(float2*)&g_gh[r8g] = make_float2(__expf(-fmaxf(acc[mt][nt][2] + bv.x, 0.0f)),
                                               __expf(-fmaxf(acc[mt][nt][3] + bv.y, 0.0f)));
        }
    __syncthreads();

    for (int idx = tid; idx < 128 * 128; idx += 256) {
        int r = idx >> 7, d = idx & 127;
        size_t gg = (size_t)(brow + r) * DD + d;
        float xv = x[gg], mv = mask[gg], dl = delta[gg], xl = xlast[gg];
        float gx = __expf(-fmaxf(fmaf(w_dg_x[d], dl, b_dg_x[d]), 0.0f));
        float xm = x_mean[b * DD + d];
        float xh = mv * xv + (1.0f - mv) * (gx * xl + (1.0f - gx) * xm);
        __nv_bfloat16 hi = __float2bfloat16(xh);
        Ahi[r * PA + d] = hi;
        Alo[r * PA + d] = __float2bfloat16(xh - __bfloat162float(hi));
        Mbf[r * PA + d] = __float2bfloat16(mv);
    }
    __syncthreads();

    const int wi[3] = {0, 2, 4};
    const int vi[3] = {1, 3, 5};
    const float* biases[3] = {b_z, b_r, b_h};
    float* outs[3] = {g_Xz, g_Xr, g_Xh};

    #pragma unroll 1
    for (int gate = 0; gate < 3; gate++) {
        stage_w(smem, SM_WHI, g_Wbh + wi[gate] * 16384);
        stage_w(smem, SM_WLO, g_Wbl + wi[gate] * 16384);
        if (tid < 128) bias_s[tid] = biases[gate][tid];
        __syncthreads();

        #pragma unroll
        for (int mt = 0; mt < 2; mt++)
            #pragma unroll
            for (int nt = 0; nt < 8; nt++)
                #pragma unroll
                for (int q = 0; q < 4; q++) acc[mt][nt][q] = 0.0f;

        const __nv_bfloat16* Ap[5] = {Ahi, Ahi, Alo, Mbf, Mbf};
        const __nv_bfloat16* Wp[5] = {Whi, Wlo, Whi, Whi, Wlo};
        #pragma unroll 1
        for (int p = 0; p < 5; p++) {
            if (p == 3) {
                __syncthreads();
                stage_w(smem, SM_WHI, g_Wbh + vi[gate] * 16384);
                stage_w(smem, SM_WLO, g_Wbl + vi[gate] * 16384);
                __syncthreads();
            }
            gpass(Ap[p], Wp[p], acc, row0, col0, lane);
        }

        float* obase = outs[gate];
        #pragma unroll
        for (int mt = 0; mt < 2; mt++)
            #pragma unroll
            for (int nt = 0; nt < 8; nt++) {
                int j0 = col0 + nt * 8 + 2 * t;
                float2 bv = *(const float2*)&bias_s[j0];
                size_t r0g = (size_t)(brow + row0 + mt * 16 + g) * HH + j0;
                size_t r8g = r0g + (size_t)8 * HH;
                *(float2*)&obase[r0g] = make_float2(acc[mt][nt][0] + bv.x, acc[mt][nt][1] + bv.y);
                *(float2*)&obase[r8g] = make_float2(acc[mt][nt][2] + bv.x, acc[mt][nt][3] + bv.y);
            }
        __syncthreads();
    }
}

// ---------------------------------------------------------------------------
// Kernel 2: recurrence. 128 CTAs x 256 threads, thread = (j, half).
// Uz/Ur live in REGISTERS (64 floats each per thread, fully unrolled k-loop);
// Uh stays in smem. One hT broadcast per k serves both z and r gates.
// Partials cross-half combined via smem xch.
// ---------------------------------------------------------------------------
#define PUS 129
#define OFS_UZ  0                         // staging [k][j] pitch 129: 16512 fl
#define OFS_UR  16512
#define OFS_UH2 33024                     // float2 [kp][j]: 16384 fl
#define OFS_HT  (OFS_UH2 + 16384)         // 49408: float[512]
#define OFS_RHT (OFS_HT + 512)            // 49920: float[512]
#define OFS_XZR (OFS_RHT + 512)           // 50432: u64[512] = 1024 fl
#define OFS_XH  (OFS_XZR + 1024)          // 51456: u64[256] = 512 fl
#define SMEMB_FL (OFS_XH + 512)           // 51968 fl = 207872 B

__global__ __launch_bounds__(256, 1)
void recurrent_kernel(const float* __restrict__ hs0,
                      const float* __restrict__ Uz, const float* __restrict__ Ur,
                      const float* __restrict__ Uh,
                      const float* __restrict__ statics,
                      const float* __restrict__ W_out, const float* __restrict__ b_out,
                      float* __restrict__ out)
{
    extern __shared__ float sm[];
    float*  UzS  = sm + OFS_UZ;               // [k][j] pitch 129 (staging)
    float*  UrS  = sm + OFS_UR;
    float2* Uh2  = (float2*)(sm + OFS_UH2);   // [kp][j]
    float*  hT   = sm + OFS_HT;               // [j][4 rows]
    float*  rhT  = sm + OFS_RHT;
    u64*    xchZR = (u64*)(sm + OFS_XZR);     // [j][4]: z01,z23,r01,r23
    u64*    xchH  = (u64*)(sm + OFS_XH);      // [j][2]: h01,h23

    const int tid  = threadIdx.x;
    const int j    = tid & 127;
    const bool h0  = tid < 128;
    const int k0   = h0 ? 0 : 64;             // k range for z/r (regs)
    const int kq0  = h0 ? 0 : 32;             // kp range for h_tilde (smem)
    const int b0   = blockIdx.x * 4;

    // stage U into smem (coalesced gmem reads, conflict-free smem writes)
    for (int idx = tid; idx < HH * HH; idx += 256) {
        int jj = idx >> 7, k = idx & 127;
        UzS[k * PUS + jj] = Uz[idx];
        UrS[k * PUS + jj] = Ur[idx];
    }
    for (int idx = tid; idx < 64 * 128; idx += 256) {
        int kp = idx >> 7, jj = idx & 127;
        Uh2[kp * 128 + jj] = make_float2(Uh[jj * 128 + 2 * kp],
                                         Uh[jj * 128 + 2 * kp + 1]);
    }

    float hreg[4], cG[4], cXz[4], cXr[4], cXh[4], zg[4];
    if (h0) {
        #pragma unroll
        for (int r = 0; r < 4; r++) {
            hreg[r] = hs0[(b0 + r) * HH + j];
            int g = ((b0 + r) * TT) * HH + j;
            cG[r] = g_gh[g]; cXz[r] = g_Xz[g]; cXr[r] = g_Xr[g]; cXh[r] = g_Xh[g];
        }
    }
    __syncthreads();

    // copy this thread's U slice into registers (conflict-free LDS: lanes read
    // consecutive j at fixed k)
    float uzr_[64], urr_[64];
    #pragma unroll
    for (int kk = 0; kk < 64; kk++) {
        uzr_[kk] = UzS[(k0 + kk) * PUS + j];
        urr_[kk] = UrS[(k0 + kk) * PUS + j];
    }

    u64 sz01 = 0, sz23 = 0, sr01 = 0, sr23 = 0, sh01 = 0, sh23 = 0;

    #pragma unroll 1
    for (int t = 0; t < TT; t++) {
        if (h0) {
            #pragma unroll
            for (int r = 0; r < 4; r++) hreg[r] *= cG[r];
            *(float4*)&hT[j * 4] = make_float4(hreg[0], hreg[1], hreg[2], hreg[3]);
        }
        __syncthreads();   // B1: hT published

        // snapshot seeds, then prefetch t+1 (half0)
        if (h0) {
            sz01 = packab(cXz[0], cXz[1]); sz23 = packab(cXz[2], cXz[3]);
            sr01 = packab(cXr[0], cXr[1]); sr23 = packab(cXr[2], cXr[3]);
            sh01 = packab(cXh[0], cXh[1]); sh23 = packab(cXh[2], cXh[3]);
            if (t + 1 < TT) {
                #pragma unroll
                for (int r = 0; r < 4; r++) {
                    int g = ((b0 + r) * TT + t + 1) * HH + j;
                    cG[r] = g_gh[g]; cXz[r] = g_Xz[g];
                    cXr[r] = g_Xr[g]; cXh[r] = g_Xh[g];
                }
            }
        }

        // ---- fused z+r partials over this half's k range, U from REGISTERS ----
        u64 az01 = 0, az23 = 0, ar01 = 0, ar23 = 0;
        #pragma unroll
        for (int kk = 0; kk < 64; kk++) {
            F4U2 hv; hv.f = *(const float4*)&hT[(k0 + kk) * 4];
            u64 uz2 = pack2(uzr_[kk]);
            u64 ur2 = pack2(urr_[kk]);
            az01 = ffma2(hv.u[0], uz2, az01);
            az23 = ffma2(hv.u[1], uz2, az23);
            ar01 = ffma2(hv.u[0], ur2, ar01);
            ar23 = ffma2(hv.u[1], ur2, ar23);
        }

        if (!h0) {
            xchZR[4 * j]     = az01;
            xchZR[4 * j + 1] = az23;
            xchZR[4 * j + 2] = ar01;
            xchZR[4 * j + 3] = ar23;
        }
        __syncthreads();   // B2: z/r partials exchanged

        if (h0) {
            u64 qz01 = xchZR[4 * j],     qz23 = xchZR[4 * j + 1];
            u64 qr01 = xchZR[4 * j + 2], qr23 = xchZR[4 * j + 3];
            float2 z01 = unpk(add2(add2(az01, qz01), sz01));
            float2 z23 = unpk(add2(add2(az23, qz23), sz23));
            float2 r01 = unpk(add2(add2(ar01, qr01), sr01));
            float2 r23 = unpk(add2(add2(ar23, qr23), sr23));
            zg[0] = 1.0f / (1.0f + __expf(-z01.x));
            zg[1] = 1.0f / (1.0f + __expf(-z01.y));
            zg[2] = 1.0f / (1.0f + __expf(-z23.x));
            zg[3] = 1.0f / (1.0f + __expf(-z23.y));
            float rg0 = 1.0f / (1.0f + __expf(-r01.x));
            float rg1 = 1.0f / (1.0f + __expf(-r01.y));
            float rg2 = 1.0f / (1.0f + __expf(-r23.x));
            float rg3 = 1.0f / (1.0f + __expf(-r23.y));
            *(float4*)&rhT[j * 4] = make_float4(rg0 * hreg[0], rg1 * hreg[1],
                                                rg2 * hreg[2], rg3 * hreg[3]);
        }
        __syncthreads();   // B3: rhT published

        // ---- h_tilde partials over this half's kp range (Uh from smem) ----
        u64 ah01 = 0, ah23 = 0;
        #pragma unroll 8
        for (int kp = kq0; kp < kq0 + 32; kp++) {
            int k4 = kp * 8;
            F4U2 re; re.f = *(const float4*)&rhT[k4];
            F4U2 ro; ro.f = *(const float4*)&rhT[k4 + 4];
            float2 u2 = Uh2[kp * 128 + j];
            u64 uhe = pack2(u2.x), uho = pack2(u2.y);
            ah01 = ffma2(re.u[0], uhe, ah01);
            ah23 = ffma2(re.u[1], uhe, ah23);
            ah01 = ffma2(ro.u[0], uho, ah01);
            ah23 = ffma2(ro.u[1], uho, ah23);
        }

        if (!h0) {
            xchH[2 * j]     = ah01;
            xchH[2 * j + 1] = ah23;
        }
        __syncthreads();   // B4: h_tilde partials exchanged

        if (h0) {
            float2 p01 = unpk(add2(add2(ah01, xchH[2 * j]), sh01));
            float2 p23 = unpk(add2(add2(ah23, xchH[2 * j + 1]), sh23));
            float pre[4] = {p01.x, p01.y, p23.x, p23.y};
            #pragma unroll
            for (int r = 0; r < 4; r++) {
                float ht = 2.0f / (1.0f + __expf(-2.0f * pre[r])) - 1.0f;
                hreg[r] = (1.0f - zg[r]) * hreg[r] + zg[r] * ht;
            }
        }
    }

    // ---- classifier ----
    __syncthreads();
    if (h0) {
        float wj = W_out[j];
        *(float4*)&hT[j * 4] = make_float4(hreg[0] * wj, hreg[1] * wj,
                                           hreg[2] * wj, hreg[3] * wj);
    }
    __syncthreads();
    for (int s = 64; s > 0; s >>= 1) {
        if (tid < s) {
            float4 a = *(const float4*)&hT[tid * 4];
            float4 c = *(const float4*)&hT[(tid + s) * 4];
            a.x += c.x; a.y += c.y; a.z += c.z; a.w += c.w;
            *(float4*)&hT[tid * 4] = a;
        }
        __syncthreads();
    }
    if (tid < 4) {
        float v = hT[tid];
        float sacc = 0.0f;
        #pragma unroll
        for (int s = 0; s < SS; s++)
            sacc = fmaf(statics[(b0 + tid) * SS + s], W_out[HH + s], sacc);
        out[b0 + tid] = v + sacc + b_out[0];
    }
}

// ---------------------------------------------------------------------------
// Launch
// ---------------------------------------------------------------------------
extern "C" void kernel_launch(void* const* d_in, const int* in_sizes, int n_in,
                              void* d_out, int out_size)
{
    const float* x       = (const float*)d_in[0];
    const float* statics = (const float*)d_in[1];
    const float* mask    = (const float*)d_in[2];
    const float* delta   = (const float*)d_in[3];
    const float* xlast   = (const float*)d_in[4];
    const float* x_mean  = (const float*)d_in[5];
    const float* hs0     = (const float*)d_in[6];
    const float* w_dg_x  = (const float*)d_in[7];
    const float* b_dg_x  = (const float*)d_in[8];
    const float* W_dg_h  = (const float*)d_in[9];
    const float* b_dg_h  = (const float*)d_in[10];
    const float* W_z = (const float*)d_in[11];
    const float* U_z = (const float*)d_in[12];
    const float* V_z = (const float*)d_in[13];
    const float* b_z = (const float*)d_in[14];
    const float* W_r = (const float*)d_in[15];
    const float* U_r = (const float*)d_in[16];
    const float* V_r = (const float*)d_in[17];
    const float* b_r = (const float*)d_in[18];
    const float* W_h = (const float*)d_in[19];
    const float* U_h = (const float*)d_in[20];
    const float* V_h = (const float*)d_in[21];
    const float* b_h = (const float*)d_in[22];
    const float* W_out = (const float*)d_in[23];
    const float* b_out = (const float*)d_in[24];
    float* out = (float*)d_out;

    const int smemB = SMEMB_FL * (int)sizeof(float);   // 207872
    cudaFuncSetAttribute(precompute_mma, cudaFuncAttributeMaxDynamicSharedMemorySize, SM_TOTAL);
    cudaFuncSetAttribute(recurrent_kernel, cudaFuncAttributeMaxDynamicSharedMemorySize, smemB);

    // one no-op: ncu capture (4th launch slot) lands on recurrent_kernel
    noop_kernel<<<1, 32>>>();
    convert_w<<<7, 256>>>(W_z, V_z, W_r, V_r, W_h, V_h, W_dg_h);
    precompute_mma<<<BT / 128, 256, SM_TOTAL>>>(x, mask, delta, xlast, x_mean,
                                                w_dg_x, b_dg_x, b_dg_h, b_z, b_r, b_h);
    recurrent_kernel<<<BB / 4, 256, smemB>>>(hs0, U_z, U_r, U_h,
                                             statics, W_out, b_out, out);
}